// round 7
// baseline (speedup 1.0000x reference)
#include <cuda_runtime.h>
#include <math.h>
#include <stdint.h>

// Problem dims
#define BB 8
#define SS 16
#define HH 32
#define WW 32
#define EE 128
#define NHH 8
#define HDD 16
#define NTOK (BB*SS*HH*WW)      // 131072
#define NPIX (BB*HH*WW)          // 8192

// ---------------- scratch (device globals) ----------------------------------
__device__ float g_x1 [NTOK*EE];
__device__ float g_qkv[NTOK*3*EE];
__device__ float g_ao [NTOK*EE];
__device__ float g_xr [NTOK*EE];
__device__ float g_c  [NPIX*EE];
__device__ float g_cc [NPIX*4*EE];
// padded planar conv inputs, pair-interleaved: plane unit = [34 rows][36 cols][2 pair]
// g_padx: [s][b][chunk16][icl4][34][36][2]   (x channels, all steps, packed once)
// g_padh: [b][chunk16][icl4][34][36][2]      (h channels, rewritten each step)
#define PLANE  2448                 // 34*72
#define CHUNKSZ 9792                // 4*PLANE
#define SBSZ   156672               // 16*CHUNKSZ
__device__ float g_padx[SS*BB*SBSZ];        // 80 MB
__device__ float g_padh[BB*16*CHUNKSZ];     // 5 MB
// weights pair-interleaved: [chunk32][tap9][icl4][oc512][pair2]
__device__ float g_wp2[32*9*4*512*2];

__device__ __forceinline__ float tf32r(float x) {
    uint32_t u;
    asm("cvt.rna.tf32.f32 %0, %1;" : "=r"(u) : "f"(x));
    return __uint_as_float(u);
}
__device__ __forceinline__ uint32_t sm_u32(const void* p) {
    return (uint32_t)__cvta_generic_to_shared(p);
}
__device__ __forceinline__ void cpa16(uint32_t dst, const float* src) {
    asm volatile("cp.async.cg.shared.global [%0], [%1], 16;\n" :: "r"(dst), "l"(src));
}

// ---------------- tf32 MMA GEMM (unchanged from R6) -------------------------
template<int N_, int MODE>
__global__ void __launch_bounds__(256) gemm_mma_kernel(const float* __restrict__ Ap,
                                                       const float* __restrict__ Bm,
                                                       const float* __restrict__ Rp)
{
    extern __shared__ float gsm[];
    float* As = gsm;            // 128 x (stride 132)
    float* Bs = gsm + 16896;    // 128 x (stride 136)

    const float* A = (MODE == 0) ? Ap : (MODE == 1 ? g_x1 : g_ao);
    float*       C = (MODE == 0) ? g_x1 : (MODE == 1 ? g_qkv : g_xr);

    const int m0 = blockIdx.x * 128;
    const int n0 = blockIdx.y * 128;
    const int t = threadIdx.x, lane = t & 31, warp = t >> 5;
    const int wm = warp & 3, wn = warp >> 2;

    #pragma unroll
    for (int j = 0; j < 16; j++) {
        int idx = t + j * 256;
        int row = idx >> 5, col4 = idx & 31;
        float4 v = *(const float4*)&A[(m0 + row) * 128 + col4 * 4];
        v.x = tf32r(v.x); v.y = tf32r(v.y); v.z = tf32r(v.z); v.w = tf32r(v.w);
        *(float4*)&As[row * 132 + col4 * 4] = v;
    }
    #pragma unroll
    for (int j = 0; j < 16; j++) {
        int idx = t + j * 256;
        int k = idx >> 5, col4 = idx & 31;
        float4 v = *(const float4*)&Bm[k * N_ + n0 + col4 * 4];
        v.x = tf32r(v.x); v.y = tf32r(v.y); v.z = tf32r(v.z); v.w = tf32r(v.w);
        *(float4*)&Bs[k * 136 + col4 * 4] = v;
    }
    __syncthreads();

    float acc[2][8][4] = {};
    #pragma unroll
    for (int k8 = 0; k8 < 16; k8++) {
        uint32_t af[2][4], bfr[8][2];
        #pragma unroll
        for (int mi = 0; mi < 2; mi++) {
            const float* p = &As[(wm * 32 + mi * 16 + (lane >> 2)) * 132 + k8 * 8 + (lane & 3)];
            af[mi][0] = __float_as_uint(p[0]);
            af[mi][1] = __float_as_uint(p[8 * 132]);
            af[mi][2] = __float_as_uint(p[4]);
            af[mi][3] = __float_as_uint(p[8 * 132 + 4]);
        }
        #pragma unroll
        for (int ni = 0; ni < 8; ni++) {
            const float* p = &Bs[(k8 * 8 + (lane & 3)) * 136 + wn * 64 + ni * 8 + (lane >> 2)];
            bfr[ni][0] = __float_as_uint(p[0]);
            bfr[ni][1] = __float_as_uint(p[4 * 136]);
        }
        #pragma unroll
        for (int mi = 0; mi < 2; mi++)
            #pragma unroll
            for (int ni = 0; ni < 8; ni++) {
                asm volatile(
                    "mma.sync.aligned.m16n8k8.row.col.f32.tf32.tf32.f32 "
                    "{%0,%1,%2,%3}, {%4,%5,%6,%7}, {%8,%9}, {%0,%1,%2,%3};"
                    : "+f"(acc[mi][ni][0]), "+f"(acc[mi][ni][1]),
                      "+f"(acc[mi][ni][2]), "+f"(acc[mi][ni][3])
                    : "r"(af[mi][0]), "r"(af[mi][1]), "r"(af[mi][2]), "r"(af[mi][3]),
                      "r"(bfr[ni][0]), "r"(bfr[ni][1]));
            }
    }

    #pragma unroll
    for (int mi = 0; mi < 2; mi++)
        #pragma unroll
        for (int ni = 0; ni < 8; ni++) {
            int r0 = m0 + wm * 32 + mi * 16 + (lane >> 2);
            int cc = n0 + wn * 64 + ni * 8 + 2 * (lane & 3);
            float2 v0 = {acc[mi][ni][0], acc[mi][ni][1]};
            float2 v1 = {acc[mi][ni][2], acc[mi][ni][3]};
            if (MODE == 0) {
                v0.x = v0.x / (1.0f + expf(-v0.x)); v0.y = v0.y / (1.0f + expf(-v0.y));
                v1.x = v1.x / (1.0f + expf(-v1.x)); v1.y = v1.y / (1.0f + expf(-v1.y));
            }
            if (MODE == 2) {
                float2 r0v = *(const float2*)&Rp[r0 * N_ + cc];
                float2 r1v = *(const float2*)&Rp[(r0 + 8) * N_ + cc];
                v0.x += r0v.x; v0.y += r0v.y; v1.x += r1v.x; v1.y += r1v.y;
            }
            *(float2*)&C[r0 * N_ + cc] = v0;
            *(float2*)&C[(r0 + 8) * N_ + cc] = v1;
        }
}

// ---------------- LayerNorm (unchanged) -------------------------------------
__global__ void ln_kernel(const float* __restrict__ gamma,
                          const float* __restrict__ beta)
{
    int tok  = blockIdx.x * 8 + (threadIdx.x >> 5);
    int lane = threadIdx.x & 31;
    float4 v = *(float4*)&g_x1[tok * 128 + lane * 4];
    float s = v.x + v.y + v.z + v.w;
    float q = v.x * v.x + v.y * v.y + v.z * v.z + v.w * v.w;
    #pragma unroll
    for (int off = 16; off > 0; off >>= 1) {
        s += __shfl_xor_sync(0xFFFFFFFF, s, off);
        q += __shfl_xor_sync(0xFFFFFFFF, q, off);
    }
    float mu  = s * (1.0f / 128.0f);
    float var = q * (1.0f / 128.0f) - mu * mu;
    float rs  = rsqrtf(var + 1e-5f);
    float4 g = *(const float4*)&gamma[lane * 4];
    float4 b = *(const float4*)&beta [lane * 4];
    v.x = (v.x - mu) * rs * g.x + b.x;
    v.y = (v.y - mu) * rs * g.y + b.y;
    v.z = (v.z - mu) * rs * g.z + b.z;
    v.w = (v.w - mu) * rs * g.w + b.w;
    *(float4*)&g_x1[tok * 128 + lane * 4] = v;
}

// ---------------- Attention (unchanged from R6) -----------------------------
__global__ void __launch_bounds__(256) attn_kernel2()
{
    extern __shared__ float qs[];          // 32 rows x stride 388
    const int bid = blockIdx.x;
    const int wp = bid & 15;
    const int h  = (bid >> 4) & 31;
    const int b  = bid >> 9;
    const int w0 = wp * 2;
    const int t  = threadIdx.x;

    #pragma unroll
    for (int j = 0; j < 12; j++) {
        int idx = t + j * 256;
        int ti = idx / 96, col4 = idx % 96;
        int s_ = ti >> 1, wl = ti & 1;
        float4 v = *(const float4*)&g_qkv[(((b * 16 + s_) * 1024) + h * 32 + w0 + wl) * 384 + col4 * 4];
        *(float4*)&qs[ti * 388 + col4 * 4] = v;
    }
    __syncthreads();

    const int gl = t >> 4, sq = t & 15;
    const int nh = gl & 7, wl = gl >> 3;
    const int ti_q = sq * 2 + wl;
    const float* qrow = &qs[ti_q * 388 + nh * 48];
    float q[16];
    #pragma unroll
    for (int d = 0; d < 16; d++) q[d] = qrow[d];

    float sc[16];
    float mx = -1e30f;
    #pragma unroll
    for (int l = 0; l < 16; l++) {
        const float* krow = &qs[(l * 2 + wl) * 388 + nh * 48 + 16];
        float d = 0.0f;
        #pragma unroll
        for (int dd = 0; dd < 16; dd++) d += q[dd] * krow[dd];
        float m = (l <= sq) ? 1.0f : -1000.0f;
        sc[l] = d * 0.25f + m;
        mx = fmaxf(mx, sc[l]);
    }
    float sum = 0.0f;
    #pragma unroll
    for (int l = 0; l < 16; l++) { sc[l] = expf(sc[l] - mx); sum += sc[l]; }
    float inv = 1.0f / sum;

    float o[16] = {};
    #pragma unroll
    for (int l = 0; l < 16; l++) {
        float pl = sc[l] * inv;
        const float* vrow = &qs[(l * 2 + wl) * 388 + nh * 48 + 32];
        #pragma unroll
        for (int dd = 0; dd < 16; dd++) o[dd] += pl * vrow[dd];
    }
    __syncthreads();
    #pragma unroll
    for (int d = 0; d < 16; d++) qs[ti_q * 388 + nh * 16 + d] = o[d];
    __syncthreads();

    #pragma unroll
    for (int j = 0; j < 4; j++) {
        int idx = t + j * 256;
        int ti = idx >> 5, col4 = idx & 31;
        int s_ = ti >> 1, wl2 = ti & 1;
        float4 v = *(float4*)&qs[ti * 388 + col4 * 4];
        *(float4*)&g_ao[(((b * 16 + s_) * 1024) + h * 32 + w0 + wl2) * 128 + col4 * 4] = v;
    }
}

// ---------------- init kernels ----------------------------------------------
__global__ void zero_c_kernel()
{
    int idx = blockIdx.x * 256 + threadIdx.x;
    g_c[idx] = 0.0f;
}
__global__ void zero_padx_kernel()
{
    int idx = blockIdx.x * 256 + threadIdx.x;   // SS*BB*SBSZ = 20,054,016 exact
    g_padx[idx] = 0.0f;
}
__global__ void zero_padh_kernel()
{
    int idx = blockIdx.x * 256 + threadIdx.x;   // 1,253,376 exact
    g_padh[idx] = 0.0f;
}
// weights: convk[oc][ic][tap] -> g_wp2[chunk][tap][icl][oc][pair], ic = chunk*8+pair*4+icl
__global__ void wprep_kernel(const float* __restrict__ convk)
{
    int idx = blockIdx.x * 256 + threadIdx.x;   // 1,179,648 exact
    int pair = idx & 1;
    int t2 = idx >> 1;
    int oc = t2 & 511;
    int t3 = t2 >> 9;
    int il = t3 & 3;
    int t4 = t3 >> 2;
    int tap = t4 % 9;
    int chunk = t4 / 9;
    int ic = chunk * 8 + pair * 4 + il;
    g_wp2[idx] = tf32r(convk[(oc * 256 + ic) * 9 + tap]);
}

// ---------------- pack x for ALL steps into g_padx --------------------------
// grid (32 y, 8 b, 16 s), 256 threads
__global__ void packx_kernel()
{
    __shared__ float tile[32][33];
    const int y = blockIdx.x, b = blockIdx.y, s = blockIdx.z;
    const int t = threadIdx.x;
    const float* src = g_xr + ((b * 16 + s) * 1024 + y * 32) * 128;
    float* dstb = g_padx + (s * 8 + b) * SBSZ;

    for (int eg = 0; eg < 4; eg++) {
        #pragma unroll
        for (int it = 0; it < 4; it++) {
            int x = (t >> 5) + it * 8;
            tile[x][t & 31] = src[x * 128 + eg * 32 + (t & 31)];
        }
        __syncthreads();
        #pragma unroll
        for (int it = 0; it < 4; it++) {
            int el = (t >> 5) + it * 8;
            int e = eg * 32 + el;
            int chunk = e >> 3, pos = e & 7, pair = pos >> 2, il = pos & 3;
            int x = t & 31;
            dstb[chunk * CHUNKSZ + il * PLANE + (y + 1) * 72 + (x + 1) * 2 + pair] =
                tf32r(tile[x][el]);
        }
        __syncthreads();
    }
}

// ---------------- conv: 4 warps, warp tile 64x64, block M=128px x N=128oc ---
// grid (4 ocT, 8 yT, 8 b), 128 threads. smem: in 2x1824 (plane stride 456),
// w 2x9504 (row stride 264). All fragment loads are LDS.64 pairs.
__global__ void __launch_bounds__(128) conv_mma_kernel(int s)
{
    extern __shared__ float sh[];
    float* in_base = sh;                // 2 x 1824
    float* w_base  = sh + 2 * 1824;     // 2 x 9504

    const int b   = blockIdx.z;
    const int y0  = blockIdx.y * 4;
    const int ocB = blockIdx.x * 128;
    const int t    = threadIdx.x;
    const int lane = t & 31;
    const int warp = t >> 5;
    const int wm = warp & 1, wn = warp >> 1;
    const int icl = lane & 3, nl = lane >> 2;

    const float* padx_b = g_padx + (s * 8 + b) * SBSZ;
    const float* padh_b = g_padh + b * 16 * CHUNKSZ;
    const uint32_t sm_in = sm_u32(in_base);
    const uint32_t sm_w  = sm_u32(w_base);

    auto load_chunk = [&](int stage, int c) {
        const float* ibase = (c < 16) ? (padx_b + c * CHUNKSZ)
                                      : (padh_b + (c - 16) * CHUNKSZ);
        uint32_t id = sm_in + (uint32_t)stage * 1824u * 4u;
        #pragma unroll
        for (int j = 0; j < 4; j++) {
            int idx = t + j * 128;
            if (idx < 432) {
                int c16 = idx % 18, r = (idx / 18) % 6, il = idx / 108;
                cpa16(id + (uint32_t)(il * 456 + r * 72 + c16 * 4) * 4u,
                      ibase + il * PLANE + (y0 + r) * 72 + c16 * 4);
            }
        }
        uint32_t wd = sm_w + (uint32_t)stage * 9504u * 4u;
        const float* wbase = g_wp2 + c * 36864 + ocB * 2;
        #pragma unroll
        for (int j = 0; j < 18; j++) {
            int idx = t + j * 128;
            int c16 = idx & 63, ti = idx >> 6;     // ti = tap*4+icl
            cpa16(wd + (uint32_t)(ti * 264 + c16 * 4) * 4u,
                  wbase + ti * 1024 + c16 * 4);
        }
        asm volatile("cp.async.commit_group;\n");
    };

    float acc[4][8][4] = {};
    load_chunk(0, 0);

    for (int c = 0; c < 32; c++) {
        const int stage = c & 1;
        if (c < 31) {
            load_chunk(stage ^ 1, c + 1);
            asm volatile("cp.async.wait_group 1;\n");
        } else {
            asm volatile("cp.async.wait_group 0;\n");
        }
        __syncthreads();

        const float* in_s = in_base + stage * 1824;
        const float* w_s  = w_base  + stage * 9504;

        #pragma unroll
        for (int tp = 0; tp < 9; tp++) {
            const int ky = tp / 3, kx = tp % 3;
            uint32_t bf[8][2];
            const float* wrow = w_s + (tp * 4 + icl) * 264 + (wn * 64 + nl) * 2;
            #pragma unroll
            for (int g = 0; g < 8; g++) {
                float2 wv = *(const float2*)(wrow + g * 16);
                bf[g][0] = __float_as_uint(wv.x);
                bf[g][1] = __float_as_uint(wv.y);
            }
            #pragma unroll
            for (int f = 0; f < 4; f++) {
                int rr = 2 * wm + (f >> 1) + ky;
                int xs = (f & 1) * 16 + nl + kx;
                const float* arow = in_s + icl * 456 + rr * 72;
                float2 p0 = *(const float2*)(arow + xs * 2);
                float2 p1 = *(const float2*)(arow + (xs + 8) * 2);
                uint32_t a0 = __float_as_uint(p0.x), a1 = __float_as_uint(p1.x);
                uint32_t a2 = __float_as_uint(p0.y), a3 = __float_as_uint(p1.y);
                #pragma unroll
                for (int g = 0; g < 8; g++) {
                    asm volatile(
                        "mma.sync.aligned.m16n8k8.row.col.f32.tf32.tf32.f32 "
                        "{%0,%1,%2,%3}, {%4,%5,%6,%7}, {%8,%9}, {%0,%1,%2,%3};"
                        : "+f"(acc[f][g][0]), "+f"(acc[f][g][1]),
                          "+f"(acc[f][g][2]), "+f"(acc[f][g][3])
                        : "r"(a0), "r"(a1), "r"(a2), "r"(a3),
                          "r"(bf[g][0]), "r"(bf[g][1]));
                }
            }
        }
        __syncthreads();
    }

    #pragma unroll
    for (int f = 0; f < 4; f++) {
        int row = y0 + 2 * wm + (f >> 1);
        int x   = (f & 1) * 16 + nl;
        #pragma unroll
        for (int g = 0; g < 8; g++) {
            int n = ocB + wn * 64 + g * 8 + 2 * icl;
            float2 v0 = {acc[f][g][0], acc[f][g][1]};
            float2 v1 = {acc[f][g][2], acc[f][g][3]};
            *(float2*)&g_cc[(b * 1024 + row * 32 + x) * 512 + n] = v0;
            *(float2*)&g_cc[(b * 1024 + row * 32 + x + 8) * 512 + n] = v1;
        }
    }
}

// ---------------- LSTM gates + out + h -> planar padh -----------------------
// grid (32 y, 8 b), 256 threads
__global__ void gates_kernel(int s, float* __restrict__ out)
{
    __shared__ float hbuf[32 * 129];
    const int y = blockIdx.x, b = blockIdx.y;
    const int t = threadIdx.x;

    #pragma unroll
    for (int i = 0; i < 16; i++) {
        int lidx = i * 256 + t;
        int e = lidx & 127, x = lidx >> 7;
        int pb = b * 1024 + y * 32 + x;
        const float* cc = g_cc + pb * 512;
        float ci = cc[e];
        float cf = cc[128 + e];
        float co = cc[256 + e];
        float cg = cc[384 + e];
        float c  = g_c[pb * 128 + e];
        float si = 1.0f / (1.0f + expf(-ci));
        float sf = 1.0f / (1.0f + expf(-cf));
        float so = 1.0f / (1.0f + expf(-co));
        float cn = sf * c + si * tanhf(cg);
        float hn = so * tanhf(cn);
        g_c[pb * 128 + e] = cn;
        out[((b * 16 + s) * 1024 + y * 32 + x) * 128 + e] = hn;
        hbuf[x * 129 + e] = hn;
    }
    __syncthreads();
    #pragma unroll
    for (int j = 0; j < 16; j++) {
        int widx = j * 256 + t;
        int x = widx & 31, e = widx >> 5;
        int chunk = e >> 3, pos = e & 7, pair = pos >> 2, il = pos & 3;
        g_padh[(b * 16 + chunk) * CHUNKSZ + il * PLANE + (y + 1) * 72 + (x + 1) * 2 + pair]
            = tf32r(hbuf[x * 129 + e]);
    }
}

// ---------------- launch ----------------------------------------------------
extern "C" void kernel_launch(void* const* d_in, const int* in_sizes, int n_in,
                              void* d_out, int out_size)
{
    const float* inputs = (const float*)d_in[0];
    const float* W_proj = (const float*)d_in[1];
    const float* gamma  = (const float*)d_in[2];
    const float* beta   = (const float*)d_in[3];
    const float* W_in   = (const float*)d_in[4];
    const float* W_out  = (const float*)d_in[5];
    const float* convk  = (const float*)d_in[6];
    float* out = (float*)d_out;

    const int GEMM_SMEM = (16896 + 17408) * 4;       // 137216
    const int ATTN_SMEM = 32 * 388 * 4;              // 49664
    const int CONV_SMEM = (2 * 1824 + 2 * 9504) * 4; // 90624
    cudaFuncSetAttribute(gemm_mma_kernel<128, 0>, cudaFuncAttributeMaxDynamicSharedMemorySize, GEMM_SMEM);
    cudaFuncSetAttribute(gemm_mma_kernel<384, 1>, cudaFuncAttributeMaxDynamicSharedMemorySize, GEMM_SMEM);
    cudaFuncSetAttribute(gemm_mma_kernel<128, 2>, cudaFuncAttributeMaxDynamicSharedMemorySize, GEMM_SMEM);
    cudaFuncSetAttribute(attn_kernel2, cudaFuncAttributeMaxDynamicSharedMemorySize, ATTN_SMEM);
    cudaFuncSetAttribute(conv_mma_kernel, cudaFuncAttributeMaxDynamicSharedMemorySize, CONV_SMEM);

    // 1) x = silu(inputs @ W_proj)
    gemm_mma_kernel<128, 0><<<dim3(NTOK / 128, 1), 256, GEMM_SMEM>>>(inputs, W_proj, nullptr);
    // 2) LayerNorm (in place)
    ln_kernel<<<NTOK / 8, 256>>>(gamma, beta);
    // 3) qkv = x @ W_in
    gemm_mma_kernel<384, 1><<<dim3(NTOK / 128, 3), 256, GEMM_SMEM>>>(nullptr, W_in, nullptr);
    // 4) attention
    attn_kernel2<<<BB * HH * (WW / 2), 256, ATTN_SMEM>>>();
    // 5) x = ao @ W_out + inputs
    gemm_mma_kernel<128, 2><<<dim3(NTOK / 128, 1), 256, GEMM_SMEM>>>(nullptr, W_out, inputs);
    // 6) init: zero c, padx, padh; pack weights; pack x for all steps
    zero_c_kernel<<<(NPIX * EE) / 256, 256>>>();
    zero_padx_kernel<<<(SS * BB * SBSZ) / 256, 256>>>();
    zero_padh_kernel<<<(BB * 16 * CHUNKSZ) / 256, 256>>>();
    wprep_kernel<<<(32 * 9 * 4 * 1024) / 256, 256>>>(convk);
    packx_kernel<<<dim3(32, 8, 16), 256>>>();
    // 7) ConvLSTM scan: conv + gates only
    for (int s = 0; s < SS; s++) {
        conv_mma_kernel<<<dim3(4, 8, 8), 128, CONV_SMEM>>>(s);
        gates_kernel<<<dim3(32, 8), 256>>>(s, out);
    }
}

// round 10
// speedup vs baseline: 1.6043x; 1.6043x over previous
#include <cuda_runtime.h>
#include <cuda_fp16.h>
#include <math.h>
#include <stdint.h>

// Problem dims
#define BB 8
#define SS 16
#define HH 32
#define WW 32
#define EE 128
#define NTOK (BB*SS*HH*WW)      // 131072
#define NPIX (BB*HH*WW)          // 8192

// conv planar layout (half2 words): [chunk][j8][34 rows][36 cols]
// chunk = 16 ic; j-plane holds ic pair (chunk*16+2j, +1) as half2 per pixel
#define JPL   1224               // 34*36 half2 per j-plane
#define CHW   9792               // 8*JPL per chunk
#define SBW   78336              // 8 chunks per (s,b) x-part

// ---------------- scratch (device globals) ----------------------------------
__device__ float g_x1 [NTOK*EE];
__device__ float g_qkv[NTOK*3*EE];
__device__ float g_ao [NTOK*EE];
__device__ float g_xr [NTOK*EE];
__device__ float g_c  [NPIX*EE];
__device__ float g_cc [NPIX*4*EE];
__device__ uint32_t g_padx[SS*BB*SBW];   // 40 MB: x channels, all steps
__device__ uint32_t g_padh[BB*SBW];      // h channels, rewritten each step
__device__ uint32_t g_w2h [16*9*8*512];  // weights [chunk16][tap9][j8][oc512] half2

__device__ __forceinline__ float tf32r(float x) {
    uint32_t u;
    asm("cvt.rna.tf32.f32 %0, %1;" : "=r"(u) : "f"(x));
    return __uint_as_float(u);
}
__device__ __forceinline__ uint32_t sm_u32(const void* p) {
    return (uint32_t)__cvta_generic_to_shared(p);
}
__device__ __forceinline__ void cpa16(uint32_t dst, const void* src) {
    asm volatile("cp.async.cg.shared.global [%0], [%1], 16;\n" :: "r"(dst), "l"(src));
}
__device__ __forceinline__ uint32_t pack_h2(float a, float b) {
    __half2 h = __halves2half2(__float2half_rn(a), __float2half_rn(b));
    return *(uint32_t*)&h;
}

// ---------------- tf32 MMA GEMM (unchanged, proven) -------------------------
template<int N_, int MODE>
__global__ void __launch_bounds__(256) gemm_mma_kernel(const float* __restrict__ Ap,
                                                       const float* __restrict__ Bm,
                                                       const float* __restrict__ Rp)
{
    extern __shared__ float gsm[];
    float* As = gsm;            // 128 x (stride 132)
    float* Bs = gsm + 16896;    // 128 x (stride 136)

    const float* A = (MODE == 0) ? Ap : (MODE == 1 ? g_x1 : g_ao);
    float*       C = (MODE == 0) ? g_x1 : (MODE == 1 ? g_qkv : g_xr);

    const int m0 = blockIdx.x * 128;
    const int n0 = blockIdx.y * 128;
    const int t = threadIdx.x, lane = t & 31, warp = t >> 5;
    const int wm = warp & 3, wn = warp >> 2;

    #pragma unroll
    for (int j = 0; j < 16; j++) {
        int idx = t + j * 256;
        int row = idx >> 5, col4 = idx & 31;
        float4 v = *(const float4*)&A[(m0 + row) * 128 + col4 * 4];
        v.x = tf32r(v.x); v.y = tf32r(v.y); v.z = tf32r(v.z); v.w = tf32r(v.w);
        *(float4*)&As[row * 132 + col4 * 4] = v;
    }
    #pragma unroll
    for (int j = 0; j < 16; j++) {
        int idx = t + j * 256;
        int k = idx >> 5, col4 = idx & 31;
        float4 v = *(const float4*)&Bm[k * N_ + n0 + col4 * 4];
        v.x = tf32r(v.x); v.y = tf32r(v.y); v.z = tf32r(v.z); v.w = tf32r(v.w);
        *(float4*)&Bs[k * 136 + col4 * 4] = v;
    }
    __syncthreads();

    float acc[2][8][4] = {};
    #pragma unroll
    for (int k8 = 0; k8 < 16; k8++) {
        uint32_t af[2][4], bfr[8][2];
        #pragma unroll
        for (int mi = 0; mi < 2; mi++) {
            const float* p = &As[(wm * 32 + mi * 16 + (lane >> 2)) * 132 + k8 * 8 + (lane & 3)];
            af[mi][0] = __float_as_uint(p[0]);
            af[mi][1] = __float_as_uint(p[8 * 132]);
            af[mi][2] = __float_as_uint(p[4]);
            af[mi][3] = __float_as_uint(p[8 * 132 + 4]);
        }
        #pragma unroll
        for (int ni = 0; ni < 8; ni++) {
            const float* p = &Bs[(k8 * 8 + (lane & 3)) * 136 + wn * 64 + ni * 8 + (lane >> 2)];
            bfr[ni][0] = __float_as_uint(p[0]);
            bfr[ni][1] = __float_as_uint(p[4 * 136]);
        }
        #pragma unroll
        for (int mi = 0; mi < 2; mi++)
            #pragma unroll
            for (int ni = 0; ni < 8; ni++) {
                asm volatile(
                    "mma.sync.aligned.m16n8k8.row.col.f32.tf32.tf32.f32 "
                    "{%0,%1,%2,%3}, {%4,%5,%6,%7}, {%8,%9}, {%0,%1,%2,%3};"
                    : "+f"(acc[mi][ni][0]), "+f"(acc[mi][ni][1]),
                      "+f"(acc[mi][ni][2]), "+f"(acc[mi][ni][3])
                    : "r"(af[mi][0]), "r"(af[mi][1]), "r"(af[mi][2]), "r"(af[mi][3]),
                      "r"(bfr[ni][0]), "r"(bfr[ni][1]));
            }
    }

    #pragma unroll
    for (int mi = 0; mi < 2; mi++)
        #pragma unroll
        for (int ni = 0; ni < 8; ni++) {
            int r0 = m0 + wm * 32 + mi * 16 + (lane >> 2);
            int cc = n0 + wn * 64 + ni * 8 + 2 * (lane & 3);
            float2 v0 = {acc[mi][ni][0], acc[mi][ni][1]};
            float2 v1 = {acc[mi][ni][2], acc[mi][ni][3]};
            if (MODE == 0) {
                v0.x = v0.x / (1.0f + expf(-v0.x)); v0.y = v0.y / (1.0f + expf(-v0.y));
                v1.x = v1.x / (1.0f + expf(-v1.x)); v1.y = v1.y / (1.0f + expf(-v1.y));
            }
            if (MODE == 2) {
                float2 r0v = *(const float2*)&Rp[r0 * N_ + cc];
                float2 r1v = *(const float2*)&Rp[(r0 + 8) * N_ + cc];
                v0.x += r0v.x; v0.y += r0v.y; v1.x += r1v.x; v1.y += r1v.y;
            }
            *(float2*)&C[r0 * N_ + cc] = v0;
            *(float2*)&C[(r0 + 8) * N_ + cc] = v1;
        }
}

// ---------------- LayerNorm (unchanged) -------------------------------------
__global__ void ln_kernel(const float* __restrict__ gamma,
                          const float* __restrict__ beta)
{
    int tok  = blockIdx.x * 8 + (threadIdx.x >> 5);
    int lane = threadIdx.x & 31;
    float4 v = *(float4*)&g_x1[tok * 128 + lane * 4];
    float s = v.x + v.y + v.z + v.w;
    float q = v.x * v.x + v.y * v.y + v.z * v.z + v.w * v.w;
    #pragma unroll
    for (int off = 16; off > 0; off >>= 1) {
        s += __shfl_xor_sync(0xFFFFFFFF, s, off);
        q += __shfl_xor_sync(0xFFFFFFFF, q, off);
    }
    float mu  = s * (1.0f / 128.0f);
    float var = q * (1.0f / 128.0f) - mu * mu;
    float rs  = rsqrtf(var + 1e-5f);
    float4 g = *(const float4*)&gamma[lane * 4];
    float4 b = *(const float4*)&beta [lane * 4];
    v.x = (v.x - mu) * rs * g.x + b.x;
    v.y = (v.y - mu) * rs * g.y + b.y;
    v.z = (v.z - mu) * rs * g.z + b.z;
    v.w = (v.w - mu) * rs * g.w + b.w;
    *(float4*)&g_x1[tok * 128 + lane * 4] = v;
}

// ---------------- Attention (unchanged) -------------------------------------
__global__ void __launch_bounds__(256) attn_kernel2()
{
    extern __shared__ float qs[];          // 32 rows x stride 388
    const int bid = blockIdx.x;
    const int wp = bid & 15;
    const int h  = (bid >> 4) & 31;
    const int b  = bid >> 9;
    const int w0 = wp * 2;
    const int t  = threadIdx.x;

    #pragma unroll
    for (int j = 0; j < 12; j++) {
        int idx = t + j * 256;
        int ti = idx / 96, col4 = idx % 96;
        int s_ = ti >> 1, wl = ti & 1;
        float4 v = *(const float4*)&g_qkv[(((b * 16 + s_) * 1024) + h * 32 + w0 + wl) * 384 + col4 * 4];
        *(float4*)&qs[ti * 388 + col4 * 4] = v;
    }
    __syncthreads();

    const int gl = t >> 4, sq = t & 15;
    const int nh = gl & 7, wl = gl >> 3;
    const int ti_q = sq * 2 + wl;
    const float* qrow = &qs[ti_q * 388 + nh * 48];
    float q[16];
    #pragma unroll
    for (int d = 0; d < 16; d++) q[d] = qrow[d];

    float sc[16];
    float mx = -1e30f;
    #pragma unroll
    for (int l = 0; l < 16; l++) {
        const float* krow = &qs[(l * 2 + wl) * 388 + nh * 48 + 16];
        float d = 0.0f;
        #pragma unroll
        for (int dd = 0; dd < 16; dd++) d += q[dd] * krow[dd];
        float m = (l <= sq) ? 1.0f : -1000.0f;
        sc[l] = d * 0.25f + m;
        mx = fmaxf(mx, sc[l]);
    }
    float sum = 0.0f;
    #pragma unroll
    for (int l = 0; l < 16; l++) { sc[l] = expf(sc[l] - mx); sum += sc[l]; }
    float inv = 1.0f / sum;

    float o[16] = {};
    #pragma unroll
    for (int l = 0; l < 16; l++) {
        float pl = sc[l] * inv;
        const float* vrow = &qs[(l * 2 + wl) * 388 + nh * 48 + 32];
        #pragma unroll
        for (int dd = 0; dd < 16; dd++) o[dd] += pl * vrow[dd];
    }
    __syncthreads();
    #pragma unroll
    for (int d = 0; d < 16; d++) qs[ti_q * 388 + nh * 16 + d] = o[d];
    __syncthreads();

    #pragma unroll
    for (int j = 0; j < 4; j++) {
        int idx = t + j * 256;
        int ti = idx >> 5, col4 = idx & 31;
        int s_ = ti >> 1, wl2 = ti & 1;
        float4 v = *(float4*)&qs[ti * 388 + col4 * 4];
        *(float4*)&g_ao[(((b * 16 + s_) * 1024) + h * 32 + w0 + wl2) * 128 + col4 * 4] = v;
    }
}

// ---------------- init kernels ----------------------------------------------
__global__ void zero_c_kernel()
{
    int idx = blockIdx.x * 256 + threadIdx.x;
    g_c[idx] = 0.0f;
}
__global__ void zero_padx_kernel()
{
    int idx = blockIdx.x * 256 + threadIdx.x;   // SS*BB*SBW = 10,027,008 exact
    g_padx[idx] = 0u;
}
__global__ void zero_padh_kernel()
{
    int idx = blockIdx.x * 256 + threadIdx.x;   // BB*SBW = 626,688 exact
    g_padh[idx] = 0u;
}
// weights: convk[oc][ic][tap] -> g_w2h[chunk16][tap9][j8][oc512] half2 (ic0, ic0+1)
__global__ void wprep_kernel(const float* __restrict__ convk)
{
    int idx = blockIdx.x * 256 + threadIdx.x;   // 589,824 exact
    int oc = idx & 511;
    int t2 = idx >> 9;
    int j  = t2 & 7;
    int t3 = t2 >> 3;                           // 0..143
    int tap = t3 % 9;
    int chunk = t3 / 9;                         // 0..15
    int ic0 = chunk * 16 + 2 * j;
    g_w2h[idx] = pack_h2(convk[(oc * 256 + ic0) * 9 + tap],
                         convk[(oc * 256 + ic0 + 1) * 9 + tap]);
}

// ---------------- pack x for ALL steps into g_padx (fp16 pairs) -------------
// grid (32 y, 8 b, 16 s), 256 threads.
__global__ void packx_kernel()
{
    __shared__ float tile[32][129];
    const int y = blockIdx.x, b = blockIdx.y, s = blockIdx.z;
    const int t = threadIdx.x;
    const float* src = g_xr + ((b * 16 + s) * 1024 + y * 32) * 128;
    uint32_t* dstb = g_padx + (s * 8 + b) * SBW;

    #pragma unroll
    for (int i = 0; i < 16; i++) {
        int idx = i * 256 + t;
        int e = idx & 127, x = idx >> 7;
        tile[x][e] = src[x * 128 + e];
    }
    __syncthreads();
    #pragma unroll
    for (int i = 0; i < 8; i++) {
        int idx = i * 256 + t;                 // 0..2047
        int x = idx & 31, m = idx >> 5;        // m = e-pair 0..63
        int chunk = m >> 3, j = m & 7;
        dstb[(chunk * 8 + j) * JPL + (y + 1) * 36 + (x + 1)] =
            pack_h2(tile[x][2 * m], tile[x][2 * m + 1]);
    }
}

// ---------------- fp16 tensor-core conv: m16n8k16, 8 warps, cp.async x2 -----
// Block: M=128 px (4 rows x 32) x N=64 oc. Warp tile 32px x 32oc.
// 16 K-chunks of 16 ic (8 from padx, 8 from padh), 9 taps per chunk.
// smem: in 2 x 1728 words ([j8][6 rows][36]), w 2 x 5184 ([tap9 j8 = 72 rows][72])
__global__ void __launch_bounds__(256) conv_mma_kernel(int s)
{
    extern __shared__ uint32_t sh[];
    uint32_t* in_base = sh;                 // 2 x 1728
    uint32_t* w_base  = sh + 2 * 1728;      // 2 x 5184

    const int b   = blockIdx.z;
    const int y0  = blockIdx.y * 4;
    const int ocB = blockIdx.x * 64;
    const int t    = threadIdx.x;
    const int lane = t & 31;
    const int warp = t >> 5;
    const int wm = warp & 3, wn = warp >> 2;
    const int jl = lane & 3, nl = lane >> 2;

    const uint32_t* padx_b = g_padx + (s * 8 + b) * SBW;
    const uint32_t* padh_b = g_padh + b * SBW;
    const uint32_t sm_in = sm_u32(in_base);
    const uint32_t sm_w  = sm_u32(w_base);

    auto load_chunk = [&](int stage, int c) {
        const uint32_t* ibase = (c < 8) ? (padx_b + c * CHW) : (padh_b + (c - 8) * CHW);
        uint32_t id = sm_in + (uint32_t)stage * 1728u * 4u;
        #pragma unroll
        for (int k = 0; k < 2; k++) {
            int idx = t + k * 256;
            if (idx < 432) {
                int j = idx / 54, rem = idx % 54;
                int r = rem / 9, c16 = rem % 9;
                cpa16(id + (uint32_t)(j * 216 + r * 36 + c16 * 4) * 4u,
                      ibase + j * JPL + (y0 + r) * 36 + c16 * 4);
            }
        }
        uint32_t wd = sm_w + (uint32_t)stage * 5184u * 4u;
        const uint32_t* wbase = g_w2h + c * 36864 + ocB;
        #pragma unroll
        for (int k = 0; k < 5; k++) {
            int idx = t + k * 256;
            if (idx < 1152) {
                int row = idx >> 4, c16 = idx & 15;    // row = tap*8+j
                cpa16(wd + (uint32_t)(row * 72 + c16 * 4) * 4u,
                      wbase + row * 512 + c16 * 4);
            }
        }
        asm volatile("cp.async.commit_group;\n");
    };

    float acc[2][4][4] = {};
    load_chunk(0, 0);

    for (int c = 0; c < 16; c++) {
        const int stage = c & 1;
        if (c < 15) {
            load_chunk(stage ^ 1, c + 1);
            asm volatile("cp.async.wait_group 1;\n");
        } else {
            asm volatile("cp.async.wait_group 0;\n");
        }
        __syncthreads();

        const uint32_t* in_s = in_base + stage * 1728;
        const uint32_t* w_s  = w_base  + stage * 5184;

        #pragma unroll
        for (int tp = 0; tp < 9; tp++) {
            const int ky = tp / 3, kx = tp % 3;
            uint32_t bf[4][2];
            #pragma unroll
            for (int g = 0; g < 4; g++) {
                int ocl = wn * 32 + g * 8 + nl;
                bf[g][0] = w_s[(tp * 8 + jl    ) * 72 + ocl];
                bf[g][1] = w_s[(tp * 8 + jl + 4) * 72 + ocl];
            }
            const int rr = wm + ky;
            #pragma unroll
            for (int f = 0; f < 2; f++) {
                int col = f * 16 + nl + kx;
                const uint32_t* p0 = in_s + jl * 216 + rr * 36 + col;
                const uint32_t* p1 = in_s + (jl + 4) * 216 + rr * 36 + col;
                uint32_t a0 = p0[0], a1 = p0[8], a2 = p1[0], a3 = p1[8];
                #pragma unroll
                for (int g = 0; g < 4; g++) {
                    asm volatile(
                        "mma.sync.aligned.m16n8k16.row.col.f32.f16.f16.f32 "
                        "{%0,%1,%2,%3}, {%4,%5,%6,%7}, {%8,%9}, {%0,%1,%2,%3};"
                        : "+f"(acc[f][g][0]), "+f"(acc[f][g][1]),
                          "+f"(acc[f][g][2]), "+f"(acc[f][g][3])
                        : "r"(a0), "r"(a1), "r"(a2), "r"(a3),
                          "r"(bf[g][0]), "r"(bf[g][1]));
                }
            }
        }
        __syncthreads();
    }

    #pragma unroll
    for (int f = 0; f < 2; f++) {
        #pragma unroll
        for (int g = 0; g < 4; g++) {
            int n  = ocB + wn * 32 + g * 8 + 2 * (lane & 3);
            int x0 = f * 16 + nl;
            int pix0 = (y0 + wm) * 32 + x0;
            float2 v0 = {acc[f][g][0], acc[f][g][1]};
            float2 v1 = {acc[f][g][2], acc[f][g][3]};
            *(float2*)&g_cc[(b * 1024 + pix0) * 512 + n] = v0;
            *(float2*)&g_cc[(b * 1024 + pix0 + 8) * 512 + n] = v1;
        }
    }
}

// ---------------- LSTM gates + out + h -> planar fp16 padh ------------------
// grid (32 y, 8 b), 256 threads
__global__ void gates_kernel(int s, float* __restrict__ out)
{
    __shared__ float hbuf[32 * 129];
    const int y = blockIdx.x, b = blockIdx.y;
    const int t = threadIdx.x;

    #pragma unroll
    for (int i = 0; i < 16; i++) {
        int lidx = i * 256 + t;
        int e = lidx & 127, x = lidx >> 7;
        int pb = b * 1024 + y * 32 + x;
        const float* cc = g_cc + pb * 512;
        float ci = cc[e];
        float cf = cc[128 + e];
        float co = cc[256 + e];
        float cg = cc[384 + e];
        float c  = g_c[pb * 128 + e];
        float si = 1.0f / (1.0f + expf(-ci));
        float sf = 1.0f / (1.0f + expf(-cf));
        float so = 1.0f / (1.0f + expf(-co));
        float cn = sf * c + si * tanhf(cg);
        float hn = so * tanhf(cn);
        g_c[pb * 128 + e] = cn;
        out[((b * 16 + s) * 1024 + y * 32 + x) * 128 + e] = hn;
        hbuf[x * 129 + e] = hn;
    }
    __syncthreads();
    #pragma unroll
    for (int i = 0; i < 8; i++) {
        int idx = i * 256 + t;                 // 0..2047
        int x = idx & 31, m = idx >> 5;        // m = e-pair 0..63
        int chunk = m >> 3, j = m & 7;
        g_padh[(b * 8 + chunk) * CHW + j * JPL + (y + 1) * 36 + (x + 1)] =
            pack_h2(hbuf[x * 129 + 2 * m], hbuf[x * 129 + 2 * m + 1]);
    }
}

// ---------------- launch ----------------------------------------------------
extern "C" void kernel_launch(void* const* d_in, const int* in_sizes, int n_in,
                              void* d_out, int out_size)
{
    const float* inputs = (const float*)d_in[0];
    const float* W_proj = (const float*)d_in[1];
    const float* gamma  = (const float*)d_in[2];
    const float* beta   = (const float*)d_in[3];
    const float* W_in   = (const float*)d_in[4];
    const float* W_out  = (const float*)d_in[5];
    const float* convk  = (const float*)d_in[6];
    float* out = (float*)d_out;

    const int GEMM_SMEM = (16896 + 17408) * 4;       // 137216
    const int ATTN_SMEM = 32 * 388 * 4;              // 49664
    const int CONV_SMEM = (2 * 1728 + 2 * 5184) * 4; // 55296
    cudaFuncSetAttribute(gemm_mma_kernel<128, 0>, cudaFuncAttributeMaxDynamicSharedMemorySize, GEMM_SMEM);
    cudaFuncSetAttribute(gemm_mma_kernel<384, 1>, cudaFuncAttributeMaxDynamicSharedMemorySize, GEMM_SMEM);
    cudaFuncSetAttribute(gemm_mma_kernel<128, 2>, cudaFuncAttributeMaxDynamicSharedMemorySize, GEMM_SMEM);
    cudaFuncSetAttribute(attn_kernel2, cudaFuncAttributeMaxDynamicSharedMemorySize, ATTN_SMEM);
    cudaFuncSetAttribute(conv_mma_kernel, cudaFuncAttributeMaxDynamicSharedMemorySize, CONV_SMEM);

    // 1) x = silu(inputs @ W_proj)
    gemm_mma_kernel<128, 0><<<dim3(NTOK / 128, 1), 256, GEMM_SMEM>>>(inputs, W_proj, nullptr);
    // 2) LayerNorm
    ln_kernel<<<NTOK / 8, 256>>>(gamma, beta);
    // 3) qkv = x @ W_in
    gemm_mma_kernel<384, 1><<<dim3(NTOK / 128, 3), 256, GEMM_SMEM>>>(nullptr, W_in, nullptr);
    // 4) attention
    attn_kernel2<<<BB * HH * (WW / 2), 256, ATTN_SMEM>>>();
    // 5) x = ao @ W_out + inputs
    gemm_mma_kernel<128, 2><<<dim3(NTOK / 128, 1), 256, GEMM_SMEM>>>(nullptr, W_out, inputs);
    // 6) init: zero c/padx/padh, pack weights, pack x for all steps
    zero_c_kernel<<<(NPIX * EE) / 256, 256>>>();
    zero_padx_kernel<<<(SS * BB * SBW) / 256, 256>>>();
    zero_padh_kernel<<<(BB * SBW) / 256, 256>>>();
    wprep_kernel<<<(16 * 9 * 8 * 512) / 256, 256>>>(convk);
    packx_kernel<<<dim3(32, 8, 16), 256>>>();
    // 7) ConvLSTM scan
    for (int s = 0; s < SS; s++) {
        conv_mma_kernel<<<dim3(8, 8, 8), 256, CONV_SMEM>>>(s);
        gates_kernel<<<dim3(32, 8), 256>>>(s, out);
    }
}

// round 12
// speedup vs baseline: 1.8280x; 1.1395x over previous
#include <cuda_runtime.h>
#include <cuda_fp16.h>
#include <math.h>
#include <stdint.h>

// Problem dims
#define BB 8
#define SS 16
#define HH 32
#define WW 32
#define EE 128
#define NTOK (BB*SS*HH*WW)      // 131072
#define NPIX (BB*HH*WW)          // 8192

// conv planar layout (half2 words): [chunk][j8][34 rows][36 cols]
#define JPL   1224               // 34*36 half2 per j-plane
#define CHW   9792               // 8*JPL per chunk (16 ic)
#define SBW   78336              // 8 chunks per (s,b) x-part

// ---------------- scratch (device globals) ----------------------------------
__device__ float g_x1 [NTOK*EE];
__device__ float g_qkv[NTOK*3*EE];
__device__ float g_ao [NTOK*EE];
__device__ float g_xr [NTOK*EE];
__device__ float g_c  [NPIX*EE];
__device__ __align__(16) uint32_t g_padx[SS*BB*SBW];  // 40 MB: x, all steps
__device__ __align__(16) uint32_t g_padh[2*BB*SBW];   // h, PING-PONG (race fix)
// weights, permuted oc': [chunk16][tap9][j8][oc'512] half2; oc' = eg*128+gate*32+el
__device__ __align__(16) uint32_t g_w2h [16*9*8*512];

__device__ __forceinline__ float tf32r(float x) {
    uint32_t u;
    asm("cvt.rna.tf32.f32 %0, %1;" : "=r"(u) : "f"(x));
    return __uint_as_float(u);
}
__device__ __forceinline__ uint32_t sm_u32(const void* p) {
    return (uint32_t)__cvta_generic_to_shared(p);
}
__device__ __forceinline__ void cpa16(uint32_t dst, const void* src) {
    asm volatile("cp.async.cg.shared.global [%0], [%1], 16;\n" :: "r"(dst), "l"(src));
}
__device__ __forceinline__ uint32_t pack_h2(float a, float b) {
    __half2 h = __halves2half2(__float2half_rn(a), __float2half_rn(b));
    return *(uint32_t*)&h;
}

// ---------------- tf32 MMA GEMM (unchanged, proven) -------------------------
template<int N_, int MODE>
__global__ void __launch_bounds__(256) gemm_mma_kernel(const float* __restrict__ Ap,
                                                       const float* __restrict__ Bm,
                                                       const float* __restrict__ Rp)
{
    extern __shared__ float gsm[];
    float* As = gsm;            // 128 x (stride 132)
    float* Bs = gsm + 16896;    // 128 x (stride 136)

    const float* A = (MODE == 0) ? Ap : (MODE == 1 ? g_x1 : g_ao);
    float*       C = (MODE == 0) ? g_x1 : (MODE == 1 ? g_qkv : g_xr);

    const int m0 = blockIdx.x * 128;
    const int n0 = blockIdx.y * 128;
    const int t = threadIdx.x, lane = t & 31, warp = t >> 5;
    const int wm = warp & 3, wn = warp >> 2;

    #pragma unroll
    for (int j = 0; j < 16; j++) {
        int idx = t + j * 256;
        int row = idx >> 5, col4 = idx & 31;
        float4 v = *(const float4*)&A[(m0 + row) * 128 + col4 * 4];
        v.x = tf32r(v.x); v.y = tf32r(v.y); v.z = tf32r(v.z); v.w = tf32r(v.w);
        *(float4*)&As[row * 132 + col4 * 4] = v;
    }
    #pragma unroll
    for (int j = 0; j < 16; j++) {
        int idx = t + j * 256;
        int k = idx >> 5, col4 = idx & 31;
        float4 v = *(const float4*)&Bm[k * N_ + n0 + col4 * 4];
        v.x = tf32r(v.x); v.y = tf32r(v.y); v.z = tf32r(v.z); v.w = tf32r(v.w);
        *(float4*)&Bs[k * 136 + col4 * 4] = v;
    }
    __syncthreads();

    float acc[2][8][4] = {};
    #pragma unroll
    for (int k8 = 0; k8 < 16; k8++) {
        uint32_t af[2][4], bfr[8][2];
        #pragma unroll
        for (int mi = 0; mi < 2; mi++) {
            const float* p = &As[(wm * 32 + mi * 16 + (lane >> 2)) * 132 + k8 * 8 + (lane & 3)];
            af[mi][0] = __float_as_uint(p[0]);
            af[mi][1] = __float_as_uint(p[8 * 132]);
            af[mi][2] = __float_as_uint(p[4]);
            af[mi][3] = __float_as_uint(p[8 * 132 + 4]);
        }
        #pragma unroll
        for (int ni = 0; ni < 8; ni++) {
            const float* p = &Bs[(k8 * 8 + (lane & 3)) * 136 + wn * 64 + ni * 8 + (lane >> 2)];
            bfr[ni][0] = __float_as_uint(p[0]);
            bfr[ni][1] = __float_as_uint(p[4 * 136]);
        }
        #pragma unroll
        for (int mi = 0; mi < 2; mi++)
            #pragma unroll
            for (int ni = 0; ni < 8; ni++) {
                asm volatile(
                    "mma.sync.aligned.m16n8k8.row.col.f32.tf32.tf32.f32 "
                    "{%0,%1,%2,%3}, {%4,%5,%6,%7}, {%8,%9}, {%0,%1,%2,%3};"
                    : "+f"(acc[mi][ni][0]), "+f"(acc[mi][ni][1]),
                      "+f"(acc[mi][ni][2]), "+f"(acc[mi][ni][3])
                    : "r"(af[mi][0]), "r"(af[mi][1]), "r"(af[mi][2]), "r"(af[mi][3]),
                      "r"(bfr[ni][0]), "r"(bfr[ni][1]));
            }
    }

    #pragma unroll
    for (int mi = 0; mi < 2; mi++)
        #pragma unroll
        for (int ni = 0; ni < 8; ni++) {
            int r0 = m0 + wm * 32 + mi * 16 + (lane >> 2);
            int cc = n0 + wn * 64 + ni * 8 + 2 * (lane & 3);
            float2 v0 = {acc[mi][ni][0], acc[mi][ni][1]};
            float2 v1 = {acc[mi][ni][2], acc[mi][ni][3]};
            if (MODE == 0) {
                v0.x = v0.x / (1.0f + expf(-v0.x)); v0.y = v0.y / (1.0f + expf(-v0.y));
                v1.x = v1.x / (1.0f + expf(-v1.x)); v1.y = v1.y / (1.0f + expf(-v1.y));
            }
            if (MODE == 2) {
                float2 r0v = *(const float2*)&Rp[r0 * N_ + cc];
                float2 r1v = *(const float2*)&Rp[(r0 + 8) * N_ + cc];
                v0.x += r0v.x; v0.y += r0v.y; v1.x += r1v.x; v1.y += r1v.y;
            }
            *(float2*)&C[r0 * N_ + cc] = v0;
            *(float2*)&C[(r0 + 8) * N_ + cc] = v1;
        }
}

// ---------------- LayerNorm (unchanged) -------------------------------------
__global__ void ln_kernel(const float* __restrict__ gamma,
                          const float* __restrict__ beta)
{
    int tok  = blockIdx.x * 8 + (threadIdx.x >> 5);
    int lane = threadIdx.x & 31;
    float4 v = *(float4*)&g_x1[tok * 128 + lane * 4];
    float s = v.x + v.y + v.z + v.w;
    float q = v.x * v.x + v.y * v.y + v.z * v.z + v.w * v.w;
    #pragma unroll
    for (int off = 16; off > 0; off >>= 1) {
        s += __shfl_xor_sync(0xFFFFFFFF, s, off);
        q += __shfl_xor_sync(0xFFFFFFFF, q, off);
    }
    float mu  = s * (1.0f / 128.0f);
    float var = q * (1.0f / 128.0f) - mu * mu;
    float rs  = rsqrtf(var + 1e-5f);
    float4 g = *(const float4*)&gamma[lane * 4];
    float4 b = *(const float4*)&beta [lane * 4];
    v.x = (v.x - mu) * rs * g.x + b.x;
    v.y = (v.y - mu) * rs * g.y + b.y;
    v.z = (v.z - mu) * rs * g.z + b.z;
    v.w = (v.w - mu) * rs * g.w + b.w;
    *(float4*)&g_x1[tok * 128 + lane * 4] = v;
}

// ---------------- Attention (unchanged) -------------------------------------
__global__ void __launch_bounds__(256) attn_kernel2()
{
    extern __shared__ float qs[];          // 32 rows x stride 388
    const int bid = blockIdx.x;
    const int wp = bid & 15;
    const int h  = (bid >> 4) & 31;
    const int b  = bid >> 9;
    const int w0 = wp * 2;
    const int t  = threadIdx.x;

    #pragma unroll
    for (int j = 0; j < 12; j++) {
        int idx = t + j * 256;
        int ti = idx / 96, col4 = idx % 96;
        int s_ = ti >> 1, wl = ti & 1;
        float4 v = *(const float4*)&g_qkv[(((b * 16 + s_) * 1024) + h * 32 + w0 + wl) * 384 + col4 * 4];
        *(float4*)&qs[ti * 388 + col4 * 4] = v;
    }
    __syncthreads();

    const int gl = t >> 4, sq = t & 15;
    const int nh = gl & 7, wl = gl >> 3;
    const int ti_q = sq * 2 + wl;
    const float* qrow = &qs[ti_q * 388 + nh * 48];
    float q[16];
    #pragma unroll
    for (int d = 0; d < 16; d++) q[d] = qrow[d];

    float sc[16];
    float mx = -1e30f;
    #pragma unroll
    for (int l = 0; l < 16; l++) {
        const float* krow = &qs[(l * 2 + wl) * 388 + nh * 48 + 16];
        float d = 0.0f;
        #pragma unroll
        for (int dd = 0; dd < 16; dd++) d += q[dd] * krow[dd];
        float m = (l <= sq) ? 1.0f : -1000.0f;
        sc[l] = d * 0.25f + m;
        mx = fmaxf(mx, sc[l]);
    }
    float sum = 0.0f;
    #pragma unroll
    for (int l = 0; l < 16; l++) { sc[l] = expf(sc[l] - mx); sum += sc[l]; }
    float inv = 1.0f / sum;

    float o[16] = {};
    #pragma unroll
    for (int l = 0; l < 16; l++) {
        float pl = sc[l] * inv;
        const float* vrow = &qs[(l * 2 + wl) * 388 + nh * 48 + 32];
        #pragma unroll
        for (int dd = 0; dd < 16; dd++) o[dd] += pl * vrow[dd];
    }
    __syncthreads();
    #pragma unroll
    for (int d = 0; d < 16; d++) qs[ti_q * 388 + nh * 16 + d] = o[d];
    __syncthreads();

    #pragma unroll
    for (int j = 0; j < 4; j++) {
        int idx = t + j * 256;
        int ti = idx >> 5, col4 = idx & 31;
        int s_ = ti >> 1, wl2 = ti & 1;
        float4 v = *(float4*)&qs[ti * 388 + col4 * 4];
        *(float4*)&g_ao[(((b * 16 + s_) * 1024) + h * 32 + w0 + wl2) * 128 + col4 * 4] = v;
    }
}

// ---------------- init kernels ----------------------------------------------
__global__ void zero_c_kernel()
{
    int idx = blockIdx.x * 256 + threadIdx.x;
    g_c[idx] = 0.0f;
}
__global__ void zero_padh_kernel()
{
    // zero buffer 0 only (read at s=0). Buffer 1's interior is fully
    // overwritten by s=0's epilogue before s=1 reads it; borders of both
    // buffers are never written and stay zero from module load.
    int idx = blockIdx.x * 256 + threadIdx.x;   // BB*SBW = 626,688 exact
    g_padh[idx] = 0u;
}
// weights: convk[oc][ic][tap] -> g_w2h[chunk16][tap9][j8][oc'512] half2 (ic0, ic0+1)
// oc' = eg*128 + gate*32 + el  <->  oc_orig = gate*128 + eg*32 + el
__global__ void wprep_kernel(const float* __restrict__ convk)
{
    int idx = blockIdx.x * 256 + threadIdx.x;   // 589,824 exact
    int ocp = idx & 511;
    int t2 = idx >> 9;
    int j  = t2 & 7;
    int t3 = t2 >> 3;                           // 0..143
    int tap = t3 % 9;
    int chunk = t3 / 9;                         // 0..15
    int eg   = ocp >> 7;
    int gate = (ocp >> 5) & 3;
    int el   = ocp & 31;
    int oc   = gate * 128 + eg * 32 + el;
    int ic0  = chunk * 16 + 2 * j;
    g_w2h[idx] = pack_h2(convk[(oc * 256 + ic0) * 9 + tap],
                         convk[(oc * 256 + ic0 + 1) * 9 + tap]);
}

// ---------------- pack x for ALL steps into g_padx (fp16 pairs) -------------
__global__ void packx_kernel()
{
    __shared__ float tile[32][129];
    const int y = blockIdx.x, b = blockIdx.y, s = blockIdx.z;
    const int t = threadIdx.x;
    const float* src = g_xr + ((b * 16 + s) * 1024 + y * 32) * 128;
    uint32_t* dstb = g_padx + (s * 8 + b) * SBW;

    #pragma unroll
    for (int i = 0; i < 16; i++) {
        int idx = i * 256 + t;
        int e = idx & 127, x = idx >> 7;
        tile[x][e] = src[x * 128 + e];
    }
    __syncthreads();
    #pragma unroll
    for (int i = 0; i < 8; i++) {
        int idx = i * 256 + t;                 // 0..2047
        int x = idx & 31, m = idx >> 5;        // m = e-pair 0..63
        int chunk = m >> 3, j = m & 7;
        dstb[(chunk * 8 + j) * JPL + (y + 1) * 36 + (x + 1)] =
            pack_h2(tile[x][2 * m], tile[x][2 * m + 1]);
    }
}

// ---------------- fused conv + LSTM gates (padh ping-pong) -------------------
// Block: M=128 px (4 rows x 32) x N=128 oc' (= one eg: all 4 gates x 32 e).
// 8 warps: wm 0..3 (row), wn 0..1; warp tile 32px x 64oc'.
// Reads h from g_padh[s&1], writes h to g_padh[(s+1)&1] -> no cross-block race.
__global__ void __launch_bounds__(256) conv_fused_kernel(int s, float* __restrict__ out)
{
    extern __shared__ uint32_t sh[];
    uint32_t* in_base = sh;                 // 2 x 1728
    uint32_t* w_base  = sh + 2 * 1728;      // 2 x 9792
    float*    Cs      = (float*)sh;         // epilogue alias: 128 x 132

    const int b   = blockIdx.z;
    const int y0  = blockIdx.y * 4;
    const int eg  = blockIdx.x;             // oc' block = eg*128
    const int t    = threadIdx.x;
    const int lane = t & 31;
    const int warp = t >> 5;
    const int wm = warp & 3, wn = warp >> 2;
    const int jl = lane & 3, nl = lane >> 2;

    const uint32_t* padx_b = g_padx + (s * 8 + b) * SBW;
    const uint32_t* padh_r = g_padh + (s & 1) * (BB * SBW) + b * SBW;       // read: h[s-1]
    uint32_t*       padh_w = g_padh + ((s + 1) & 1) * (BB * SBW);           // write: h[s]
    const uint32_t sm_in = sm_u32(in_base);
    const uint32_t sm_w  = sm_u32(w_base);

    auto load_chunk = [&](int stage, int c) {
        const uint32_t* ibase = (c < 8) ? (padx_b + c * CHW) : (padh_r + (c - 8) * CHW);
        uint32_t id = sm_in + (uint32_t)stage * 1728u * 4u;
        #pragma unroll
        for (int k = 0; k < 2; k++) {
            int idx = t + k * 256;
            if (idx < 432) {
                int j = idx / 54, rem = idx % 54;
                int r = rem / 9, c16 = rem % 9;
                cpa16(id + (uint32_t)(j * 216 + r * 36 + c16 * 4) * 4u,
                      ibase + j * JPL + (y0 + r) * 36 + c16 * 4);
            }
        }
        uint32_t wd = sm_w + (uint32_t)stage * 9792u * 4u;
        const uint32_t* wbase = g_w2h + c * 36864 + eg * 128;
        #pragma unroll
        for (int k = 0; k < 9; k++) {
            int idx = t + k * 256;              // 0..2303
            int row = idx >> 5, c16 = idx & 31; // row = tap*8+j (72)
            cpa16(wd + (uint32_t)(row * 136 + c16 * 4) * 4u,
                  wbase + row * 512 + c16 * 4);
        }
        asm volatile("cp.async.commit_group;\n");
    };

    float acc[2][8][4] = {};
    load_chunk(0, 0);

    for (int c = 0; c < 16; c++) {
        const int stage = c & 1;
        if (c < 15) {
            load_chunk(stage ^ 1, c + 1);
            asm volatile("cp.async.wait_group 1;\n");
        } else {
            asm volatile("cp.async.wait_group 0;\n");
        }
        __syncthreads();

        const uint32_t* in_s = in_base + stage * 1728;
        const uint32_t* w_s  = w_base  + stage * 9792;

        #pragma unroll
        for (int tp = 0; tp < 9; tp++) {
            const int ky = tp / 3, kx = tp % 3;
            uint32_t bf[8][2];
            #pragma unroll
            for (int g = 0; g < 8; g++) {
                int ocl = wn * 64 + g * 8 + nl;
                bf[g][0] = w_s[(tp * 8 + jl    ) * 136 + ocl];
                bf[g][1] = w_s[(tp * 8 + jl + 4) * 136 + ocl];
            }
            const int rr = wm + ky;
            #pragma unroll
            for (int f = 0; f < 2; f++) {
                int col = f * 16 + nl + kx;
                const uint32_t* p0 = in_s + jl * 216 + rr * 36 + col;
                const uint32_t* p1 = in_s + (jl + 4) * 216 + rr * 36 + col;
                uint32_t a0 = p0[0], a1 = p0[8], a2 = p1[0], a3 = p1[8];
                #pragma unroll
                for (int g = 0; g < 8; g++) {
                    asm volatile(
                        "mma.sync.aligned.m16n8k16.row.col.f32.f16.f16.f32 "
                        "{%0,%1,%2,%3}, {%4,%5,%6,%7}, {%8,%9}, {%0,%1,%2,%3};"
                        : "+f"(acc[f][g][0]), "+f"(acc[f][g][1]),
                          "+f"(acc[f][g][2]), "+f"(acc[f][g][3])
                        : "r"(a0), "r"(a1), "r"(a2), "r"(a3),
                          "r"(bf[g][0]), "r"(bf[g][1]));
                }
            }
        }
        __syncthreads();
    }

    // ---- epilogue: stage C tile in smem (aliases pipeline buffers) ----
    #pragma unroll
    for (int f = 0; f < 2; f++) {
        #pragma unroll
        for (int g = 0; g < 8; g++) {
            int mloc = wm * 32 + f * 16 + nl;
            int ocl  = wn * 64 + g * 8 + 2 * (lane & 3);
            *(float2*)&Cs[mloc * 132 + ocl]       = make_float2(acc[f][g][0], acc[f][g][1]);
            *(float2*)&Cs[(mloc + 8) * 132 + ocl] = make_float2(acc[f][g][2], acc[f][g][3]);
        }
    }
    __syncthreads();

    // ---- gates: each thread handles 16 (px, el) quads ----
    __half* padh_h = (__half*)padh_w;
    #pragma unroll
    for (int i = 0; i < 16; i++) {
        int q  = i * 256 + t;              // 0..4095
        int el = q & 31, px = q >> 5;      // px 0..127
        int row = px >> 5, x = px & 31;
        int y = y0 + row;
        float ci = Cs[px * 132 + el];
        float cf = Cs[px * 132 + 32 + el];
        float co = Cs[px * 132 + 64 + el];
        float cg = Cs[px * 132 + 96 + el];
        int e  = eg * 32 + el;
        int pb = b * 1024 + y * 32 + x;
        float c  = g_c[pb * 128 + e];
        float si = 1.0f / (1.0f + expf(-ci));
        float sf = 1.0f / (1.0f + expf(-cf));
        float so = 1.0f / (1.0f + expf(-co));
        float cn = sf * c + si * tanhf(cg);
        float hn = so * tanhf(cn);
        g_c[pb * 128 + e] = cn;
        out[((b * 16 + s) * 1024 + y * 32 + x) * 128 + e] = hn;
        int chunk_h = e >> 4, j = (e & 15) >> 1, pos = e & 1;
        padh_h[((((b * 8 + chunk_h) * CHW) + j * JPL + (y + 1) * 36 + (x + 1)) << 1) | pos]
            = __float2half_rn(hn);
    }
}

// ---------------- launch ----------------------------------------------------
extern "C" void kernel_launch(void* const* d_in, const int* in_sizes, int n_in,
                              void* d_out, int out_size)
{
    const float* inputs = (const float*)d_in[0];
    const float* W_proj = (const float*)d_in[1];
    const float* gamma  = (const float*)d_in[2];
    const float* beta   = (const float*)d_in[3];
    const float* W_in   = (const float*)d_in[4];
    const float* W_out  = (const float*)d_in[5];
    const float* convk  = (const float*)d_in[6];
    float* out = (float*)d_out;

    const int GEMM_SMEM = (16896 + 17408) * 4;       // 137216
    const int ATTN_SMEM = 32 * 388 * 4;              // 49664
    const int CONV_SMEM = (2 * 1728 + 2 * 9792) * 4; // 92160
    cudaFuncSetAttribute(gemm_mma_kernel<128, 0>, cudaFuncAttributeMaxDynamicSharedMemorySize, GEMM_SMEM);
    cudaFuncSetAttribute(gemm_mma_kernel<384, 1>, cudaFuncAttributeMaxDynamicSharedMemorySize, GEMM_SMEM);
    cudaFuncSetAttribute(gemm_mma_kernel<128, 2>, cudaFuncAttributeMaxDynamicSharedMemorySize, GEMM_SMEM);
    cudaFuncSetAttribute(attn_kernel2, cudaFuncAttributeMaxDynamicSharedMemorySize, ATTN_SMEM);
    cudaFuncSetAttribute(conv_fused_kernel, cudaFuncAttributeMaxDynamicSharedMemorySize, CONV_SMEM);

    // 1) x = silu(inputs @ W_proj)
    gemm_mma_kernel<128, 0><<<dim3(NTOK / 128, 1), 256, GEMM_SMEM>>>(inputs, W_proj, nullptr);
    // 2) LayerNorm
    ln_kernel<<<NTOK / 8, 256>>>(gamma, beta);
    // 3) qkv = x @ W_in
    gemm_mma_kernel<384, 1><<<dim3(NTOK / 128, 3), 256, GEMM_SMEM>>>(nullptr, W_in, nullptr);
    // 4) attention
    attn_kernel2<<<BB * HH * (WW / 2), 256, ATTN_SMEM>>>();
    // 5) x = ao @ W_out + inputs
    gemm_mma_kernel<128, 2><<<dim3(NTOK / 128, 1), 256, GEMM_SMEM>>>(nullptr, W_out, inputs);
    // 6) init: zero c + padh buf0; pack weights + x (padx borders stay zero)
    zero_c_kernel<<<(NPIX * EE) / 256, 256>>>();
    zero_padh_kernel<<<(BB * SBW) / 256, 256>>>();
    wprep_kernel<<<(16 * 9 * 8 * 512) / 256, 256>>>(convk);
    packx_kernel<<<dim3(32, 8, 16), 256>>>();
    // 7) ConvLSTM scan: ONE fused kernel per step, ping-pong h buffers
    for (int s = 0; s < SS; s++) {
        conv_fused_kernel<<<dim3(4, 8, 8), 256, CONV_SMEM>>>(s, out);
    }
}

// round 13
// speedup vs baseline: 1.9218x; 1.0513x over previous
#include <cuda_runtime.h>
#include <cuda_fp16.h>
#include <math.h>
#include <stdint.h>

// Problem dims
#define BB 8
#define SS 16
#define HH 32
#define WW 32
#define EE 128
#define NTOK (BB*SS*HH*WW)      // 131072
#define NPIX (BB*HH*WW)          // 8192

// conv planar layout (half2 words): [chunk][j8][34 rows][36 cols]
#define JPL   1224               // 34*36 half2 per j-plane
#define CHW   9792               // 8*JPL per chunk (16 ic)
#define SBW   78336              // 8 chunks per (s,b) x-part

// ---------------- scratch (device globals) ----------------------------------
__device__ float g_qkv[NTOK*3*EE];
__device__ float g_ao [NTOK*EE];
__device__ float g_c  [NPIX*EE];
__device__ __align__(16) uint32_t g_padx[SS*BB*SBW];  // 40 MB: x, all steps
__device__ __align__(16) uint32_t g_padh[2*BB*SBW];   // h, ping-pong
__device__ __align__(16) uint32_t g_w2h [16*9*8*512]; // [chunk16][tap9][j8][oc'512]

__device__ __forceinline__ float tf32r(float x) {
    uint32_t u;
    asm("cvt.rna.tf32.f32 %0, %1;" : "=r"(u) : "f"(x));
    return __uint_as_float(u);
}
__device__ __forceinline__ uint32_t sm_u32(const void* p) {
    return (uint32_t)__cvta_generic_to_shared(p);
}
__device__ __forceinline__ void cpa16(uint32_t dst, const void* src) {
    asm volatile("cp.async.cg.shared.global [%0], [%1], 16;\n" :: "r"(dst), "l"(src));
}
__device__ __forceinline__ uint32_t pack_h2(float a, float b) {
    __half2 h = __halves2half2(__float2half_rn(a), __float2half_rn(b));
    return *(uint32_t*)&h;
}

#define MMA_TF32(acc, af, bf)                                              \
    asm volatile(                                                          \
        "mma.sync.aligned.m16n8k8.row.col.f32.tf32.tf32.f32 "              \
        "{%0,%1,%2,%3}, {%4,%5,%6,%7}, {%8,%9}, {%0,%1,%2,%3};"            \
        : "+f"(acc[0]), "+f"(acc[1]), "+f"(acc[2]), "+f"(acc[3])           \
        : "r"(af[0]), "r"(af[1]), "r"(af[2]), "r"(af[3]),                  \
          "r"(bf[0]), "r"(bf[1]))

// ---------------- fused front: silu(in@Wp) -> LN -> @W_in -> g_qkv ----------
// Block: 128 tokens x full 128 cols. 8 warps (wm row-quarter, wn col-half).
// smem: As 128x132 fp32 (A tile, then LN'd x), Bs 128x136 fp32 (B tiles).
__global__ void __launch_bounds__(256) front_fused_kernel(
    const float* __restrict__ inputs, const float* __restrict__ Wp,
    const float* __restrict__ Win,
    const float* __restrict__ gamma, const float* __restrict__ beta)
{
    extern __shared__ float gsm[];
    float* As = gsm;            // 128 x 132
    float* Bs = gsm + 16896;    // 128 x 136

    const int m0 = blockIdx.x * 128;
    const int t = threadIdx.x, lane = t & 31, warp = t >> 5;
    const int wm = warp & 3, wn = warp >> 2;

    // ---- load A (inputs) + B (W_proj), tf32-rounded ----
    #pragma unroll
    for (int j = 0; j < 16; j++) {
        int idx = t + j * 256;
        int row = idx >> 5, col4 = idx & 31;
        float4 v = *(const float4*)&inputs[(m0 + row) * 128 + col4 * 4];
        v.x = tf32r(v.x); v.y = tf32r(v.y); v.z = tf32r(v.z); v.w = tf32r(v.w);
        *(float4*)&As[row * 132 + col4 * 4] = v;
    }
    #pragma unroll
    for (int j = 0; j < 16; j++) {
        int idx = t + j * 256;
        int k = idx >> 5, col4 = idx & 31;
        float4 v = *(const float4*)&Wp[k * 128 + col4 * 4];
        v.x = tf32r(v.x); v.y = tf32r(v.y); v.z = tf32r(v.z); v.w = tf32r(v.w);
        *(float4*)&Bs[k * 136 + col4 * 4] = v;
    }
    __syncthreads();

    // ---- GEMM 1: x = inputs @ W_proj ----
    float acc[2][8][4] = {};
    #pragma unroll
    for (int k8 = 0; k8 < 16; k8++) {
        uint32_t af[2][4], bfr[8][2];
        #pragma unroll
        for (int mi = 0; mi < 2; mi++) {
            const float* p = &As[(wm * 32 + mi * 16 + (lane >> 2)) * 132 + k8 * 8 + (lane & 3)];
            af[mi][0] = __float_as_uint(p[0]);
            af[mi][1] = __float_as_uint(p[8 * 132]);
            af[mi][2] = __float_as_uint(p[4]);
            af[mi][3] = __float_as_uint(p[8 * 132 + 4]);
        }
        #pragma unroll
        for (int ni = 0; ni < 8; ni++) {
            const float* p = &Bs[(k8 * 8 + (lane & 3)) * 136 + wn * 64 + ni * 8 + (lane >> 2)];
            bfr[ni][0] = __float_as_uint(p[0]);
            bfr[ni][1] = __float_as_uint(p[4 * 136]);
        }
        #pragma unroll
        for (int mi = 0; mi < 2; mi++)
            #pragma unroll
            for (int ni = 0; ni < 8; ni++)
                MMA_TF32(acc[mi][ni], af[mi], bfr[ni]);
    }
    __syncthreads();   // all warps done reading As

    // ---- silu, stage x back into As ----
    #pragma unroll
    for (int mi = 0; mi < 2; mi++)
        #pragma unroll
        for (int ni = 0; ni < 8; ni++) {
            int r = wm * 32 + mi * 16 + (lane >> 2);
            int cc = wn * 64 + ni * 8 + 2 * (lane & 3);
            float2 v0 = {acc[mi][ni][0], acc[mi][ni][1]};
            float2 v1 = {acc[mi][ni][2], acc[mi][ni][3]};
            v0.x = v0.x / (1.0f + expf(-v0.x)); v0.y = v0.y / (1.0f + expf(-v0.y));
            v1.x = v1.x / (1.0f + expf(-v1.x)); v1.y = v1.y / (1.0f + expf(-v1.y));
            *(float2*)&As[r * 132 + cc]       = v0;
            *(float2*)&As[(r + 8) * 132 + cc] = v1;
        }
    __syncthreads();

    // ---- LayerNorm in-place on As (warp w: rows w*16..w*16+15) ----
    {
        float4 g4 = *(const float4*)&gamma[lane * 4];
        float4 b4 = *(const float4*)&beta [lane * 4];
        for (int rl = 0; rl < 16; rl++) {
            int row = warp * 16 + rl;
            float4 v = *(float4*)&As[row * 132 + lane * 4];
            float s = v.x + v.y + v.z + v.w;
            float q = v.x * v.x + v.y * v.y + v.z * v.z + v.w * v.w;
            #pragma unroll
            for (int off = 16; off > 0; off >>= 1) {
                s += __shfl_xor_sync(0xFFFFFFFF, s, off);
                q += __shfl_xor_sync(0xFFFFFFFF, q, off);
            }
            float mu  = s * (1.0f / 128.0f);
            float var = q * (1.0f / 128.0f) - mu * mu;
            float rs  = rsqrtf(var + 1e-5f);
            v.x = tf32r((v.x - mu) * rs * g4.x + b4.x);
            v.y = tf32r((v.y - mu) * rs * g4.y + b4.y);
            v.z = tf32r((v.z - mu) * rs * g4.z + b4.z);
            v.w = tf32r((v.w - mu) * rs * g4.w + b4.w);
            *(float4*)&As[row * 132 + lane * 4] = v;
        }
    }
    __syncthreads();

    // ---- GEMM 2: qkv = x @ W_in, 3 column tiles through Bs ----
    for (int nt = 0; nt < 3; nt++) {
        #pragma unroll
        for (int j = 0; j < 16; j++) {
            int idx = t + j * 256;
            int k = idx >> 5, col4 = idx & 31;
            float4 v = *(const float4*)&Win[k * 384 + nt * 128 + col4 * 4];
            v.x = tf32r(v.x); v.y = tf32r(v.y); v.z = tf32r(v.z); v.w = tf32r(v.w);
            *(float4*)&Bs[k * 136 + col4 * 4] = v;
        }
        __syncthreads();

        float a2[2][8][4] = {};
        #pragma unroll
        for (int k8 = 0; k8 < 16; k8++) {
            uint32_t af[2][4], bfr[8][2];
            #pragma unroll
            for (int mi = 0; mi < 2; mi++) {
                const float* p = &As[(wm * 32 + mi * 16 + (lane >> 2)) * 132 + k8 * 8 + (lane & 3)];
                af[mi][0] = __float_as_uint(p[0]);
                af[mi][1] = __float_as_uint(p[8 * 132]);
                af[mi][2] = __float_as_uint(p[4]);
                af[mi][3] = __float_as_uint(p[8 * 132 + 4]);
            }
            #pragma unroll
            for (int ni = 0; ni < 8; ni++) {
                const float* p = &Bs[(k8 * 8 + (lane & 3)) * 136 + wn * 64 + ni * 8 + (lane >> 2)];
                bfr[ni][0] = __float_as_uint(p[0]);
                bfr[ni][1] = __float_as_uint(p[4 * 136]);
            }
            #pragma unroll
            for (int mi = 0; mi < 2; mi++)
                #pragma unroll
                for (int ni = 0; ni < 8; ni++)
                    MMA_TF32(a2[mi][ni], af[mi], bfr[ni]);
        }

        #pragma unroll
        for (int mi = 0; mi < 2; mi++)
            #pragma unroll
            for (int ni = 0; ni < 8; ni++) {
                int r0 = m0 + wm * 32 + mi * 16 + (lane >> 2);
                int cc = nt * 128 + wn * 64 + ni * 8 + 2 * (lane & 3);
                *(float2*)&g_qkv[r0 * 384 + cc]       = make_float2(a2[mi][ni][0], a2[mi][ni][1]);
                *(float2*)&g_qkv[(r0 + 8) * 384 + cc] = make_float2(a2[mi][ni][2], a2[mi][ni][3]);
            }
        __syncthreads();   // before Bs overwrite
    }
}

// ---------------- Attention (unchanged) -------------------------------------
__global__ void __launch_bounds__(256) attn_kernel2()
{
    extern __shared__ float qs[];          // 32 rows x stride 388
    const int bid = blockIdx.x;
    const int wp = bid & 15;
    const int h  = (bid >> 4) & 31;
    const int b  = bid >> 9;
    const int w0 = wp * 2;
    const int t  = threadIdx.x;

    #pragma unroll
    for (int j = 0; j < 12; j++) {
        int idx = t + j * 256;
        int ti = idx / 96, col4 = idx % 96;
        int s_ = ti >> 1, wl = ti & 1;
        float4 v = *(const float4*)&g_qkv[(((b * 16 + s_) * 1024) + h * 32 + w0 + wl) * 384 + col4 * 4];
        *(float4*)&qs[ti * 388 + col4 * 4] = v;
    }
    __syncthreads();

    const int gl = t >> 4, sq = t & 15;
    const int nh = gl & 7, wl = gl >> 3;
    const int ti_q = sq * 2 + wl;
    const float* qrow = &qs[ti_q * 388 + nh * 48];
    float q[16];
    #pragma unroll
    for (int d = 0; d < 16; d++) q[d] = qrow[d];

    float sc[16];
    float mx = -1e30f;
    #pragma unroll
    for (int l = 0; l < 16; l++) {
        const float* krow = &qs[(l * 2 + wl) * 388 + nh * 48 + 16];
        float d = 0.0f;
        #pragma unroll
        for (int dd = 0; dd < 16; dd++) d += q[dd] * krow[dd];
        float m = (l <= sq) ? 1.0f : -1000.0f;
        sc[l] = d * 0.25f + m;
        mx = fmaxf(mx, sc[l]);
    }
    float sum = 0.0f;
    #pragma unroll
    for (int l = 0; l < 16; l++) { sc[l] = expf(sc[l] - mx); sum += sc[l]; }
    float inv = 1.0f / sum;

    float o[16] = {};
    #pragma unroll
    for (int l = 0; l < 16; l++) {
        float pl = sc[l] * inv;
        const float* vrow = &qs[(l * 2 + wl) * 388 + nh * 48 + 32];
        #pragma unroll
        for (int dd = 0; dd < 16; dd++) o[dd] += pl * vrow[dd];
    }
    __syncthreads();
    #pragma unroll
    for (int d = 0; d < 16; d++) qs[ti_q * 388 + nh * 16 + d] = o[d];
    __syncthreads();

    #pragma unroll
    for (int j = 0; j < 4; j++) {
        int idx = t + j * 256;
        int ti = idx >> 5, col4 = idx & 31;
        int s_ = ti >> 1, wl2 = ti & 1;
        float4 v = *(float4*)&qs[ti * 388 + col4 * 4];
        *(float4*)&g_ao[(((b * 16 + s_) * 1024) + h * 32 + w0 + wl2) * 128 + col4 * 4] = v;
    }
}

// ---------------- out GEMM + residual + direct fp16 pack into g_padx --------
// C = g_ao @ W_out + inputs; epilogue writes half2 pairs straight to g_padx.
__global__ void __launch_bounds__(256) gemm_out_pack_kernel(
    const float* __restrict__ Wout, const float* __restrict__ inputs)
{
    extern __shared__ float gsm[];
    float* As = gsm;            // 128 x 132
    float* Bs = gsm + 16896;    // 128 x 136

    const int m0 = blockIdx.x * 128;
    const int t = threadIdx.x, lane = t & 31, warp = t >> 5;
    const int wm = warp & 3, wn = warp >> 2;

    #pragma unroll
    for (int j = 0; j < 16; j++) {
        int idx = t + j * 256;
        int row = idx >> 5, col4 = idx & 31;
        float4 v = *(const float4*)&g_ao[(m0 + row) * 128 + col4 * 4];
        v.x = tf32r(v.x); v.y = tf32r(v.y); v.z = tf32r(v.z); v.w = tf32r(v.w);
        *(float4*)&As[row * 132 + col4 * 4] = v;
    }
    #pragma unroll
    for (int j = 0; j < 16; j++) {
        int idx = t + j * 256;
        int k = idx >> 5, col4 = idx & 31;
        float4 v = *(const float4*)&Wout[k * 128 + col4 * 4];
        v.x = tf32r(v.x); v.y = tf32r(v.y); v.z = tf32r(v.z); v.w = tf32r(v.w);
        *(float4*)&Bs[k * 136 + col4 * 4] = v;
    }
    __syncthreads();

    float acc[2][8][4] = {};
    #pragma unroll
    for (int k8 = 0; k8 < 16; k8++) {
        uint32_t af[2][4], bfr[8][2];
        #pragma unroll
        for (int mi = 0; mi < 2; mi++) {
            const float* p = &As[(wm * 32 + mi * 16 + (lane >> 2)) * 132 + k8 * 8 + (lane & 3)];
            af[mi][0] = __float_as_uint(p[0]);
            af[mi][1] = __float_as_uint(p[8 * 132]);
            af[mi][2] = __float_as_uint(p[4]);
            af[mi][3] = __float_as_uint(p[8 * 132 + 4]);
        }
        #pragma unroll
        for (int ni = 0; ni < 8; ni++) {
            const float* p = &Bs[(k8 * 8 + (lane & 3)) * 136 + wn * 64 + ni * 8 + (lane >> 2)];
            bfr[ni][0] = __float_as_uint(p[0]);
            bfr[ni][1] = __float_as_uint(p[4 * 136]);
        }
        #pragma unroll
        for (int mi = 0; mi < 2; mi++)
            #pragma unroll
            for (int ni = 0; ni < 8; ni++)
                MMA_TF32(acc[mi][ni], af[mi], bfr[ni]);
    }

    #pragma unroll
    for (int mi = 0; mi < 2; mi++)
        #pragma unroll
        for (int ni = 0; ni < 8; ni++) {
            int cc = wn * 64 + ni * 8 + 2 * (lane & 3);     // even e
            int chunk = cc >> 4, jp = (cc & 15) >> 1;
            #pragma unroll
            for (int half = 0; half < 2; half++) {
                int r = m0 + wm * 32 + mi * 16 + (lane >> 2) + half * 8;
                float2 rv = *(const float2*)&inputs[r * 128 + cc];
                float vx = acc[mi][ni][half * 2 + 0] + rv.x;
                float vy = acc[mi][ni][half * 2 + 1] + rv.y;
                int b_ = r >> 14, s_ = (r >> 10) & 15, y = (r >> 5) & 31, x = r & 31;
                g_padx[(s_ * 8 + b_) * SBW + (chunk * 8 + jp) * JPL + (y + 1) * 36 + (x + 1)]
                    = pack_h2(vx, vy);
            }
        }
}

// ---------------- init: zero c + padh buf0 in one launch --------------------
__global__ void zero_init_kernel()
{
    int idx = blockIdx.x * 256 + threadIdx.x;   // 1,675,264 exact
    if (idx < NPIX * EE) g_c[idx] = 0.0f;
    else                 g_padh[idx - NPIX * EE] = 0u;
}
// weights: convk[oc][ic][tap] -> g_w2h[chunk16][tap9][j8][oc'512] half2 (ic0, ic0+1)
// oc' = eg*128 + gate*32 + el  <->  oc_orig = gate*128 + eg*32 + el
__global__ void wprep_kernel(const float* __restrict__ convk)
{
    int idx = blockIdx.x * 256 + threadIdx.x;   // 589,824 exact
    int ocp = idx & 511;
    int t2 = idx >> 9;
    int j  = t2 & 7;
    int t3 = t2 >> 3;                           // 0..143
    int tap = t3 % 9;
    int chunk = t3 / 9;                         // 0..15
    int eg   = ocp >> 7;
    int gate = (ocp >> 5) & 3;
    int el   = ocp & 31;
    int oc   = gate * 128 + eg * 32 + el;
    int ic0  = chunk * 16 + 2 * j;
    g_w2h[idx] = pack_h2(convk[(oc * 256 + ic0) * 9 + tap],
                         convk[(oc * 256 + ic0 + 1) * 9 + tap]);
}

// ---------------- fused conv + LSTM gates (padh ping-pong, unchanged) -------
__global__ void __launch_bounds__(256) conv_fused_kernel(int s, float* __restrict__ out)
{
    extern __shared__ uint32_t sh[];
    uint32_t* in_base = sh;                 // 2 x 1728
    uint32_t* w_base  = sh + 2 * 1728;      // 2 x 9792
    float*    Cs      = (float*)sh;         // epilogue alias: 128 x 132

    const int b   = blockIdx.z;
    const int y0  = blockIdx.y * 4;
    const int eg  = blockIdx.x;             // oc' block = eg*128
    const int t    = threadIdx.x;
    const int lane = t & 31;
    const int warp = t >> 5;
    const int wm = warp & 3, wn = warp >> 2;
    const int jl = lane & 3, nl = lane >> 2;

    const uint32_t* padx_b = g_padx + (s * 8 + b) * SBW;
    const uint32_t* padh_r = g_padh + (s & 1) * (BB * SBW) + b * SBW;
    uint32_t*       padh_w = g_padh + ((s + 1) & 1) * (BB * SBW);
    const uint32_t sm_in = sm_u32(in_base);
    const uint32_t sm_w  = sm_u32(w_base);

    auto load_chunk = [&](int stage, int c) {
        const uint32_t* ibase = (c < 8) ? (padx_b + c * CHW) : (padh_r + (c - 8) * CHW);
        uint32_t id = sm_in + (uint32_t)stage * 1728u * 4u;
        #pragma unroll
        for (int k = 0; k < 2; k++) {
            int idx = t + k * 256;
            if (idx < 432) {
                int j = idx / 54, rem = idx % 54;
                int r = rem / 9, c16 = rem % 9;
                cpa16(id + (uint32_t)(j * 216 + r * 36 + c16 * 4) * 4u,
                      ibase + j * JPL + (y0 + r) * 36 + c16 * 4);
            }
        }
        uint32_t wd = sm_w + (uint32_t)stage * 9792u * 4u;
        const uint32_t* wbase = g_w2h + c * 36864 + eg * 128;
        #pragma unroll
        for (int k = 0; k < 9; k++) {
            int idx = t + k * 256;
            int row = idx >> 5, c16 = idx & 31;
            cpa16(wd + (uint32_t)(row * 136 + c16 * 4) * 4u,
                  wbase + row * 512 + c16 * 4);
        }
        asm volatile("cp.async.commit_group;\n");
    };

    float acc[2][8][4] = {};
    load_chunk(0, 0);

    for (int c = 0; c < 16; c++) {
        const int stage = c & 1;
        if (c < 15) {
            load_chunk(stage ^ 1, c + 1);
            asm volatile("cp.async.wait_group 1;\n");
        } else {
            asm volatile("cp.async.wait_group 0;\n");
        }
        __syncthreads();

        const uint32_t* in_s = in_base + stage * 1728;
        const uint32_t* w_s  = w_base  + stage * 9792;

        #pragma unroll
        for (int tp = 0; tp < 9; tp++) {
            const int ky = tp / 3, kx = tp % 3;
            uint32_t bf[8][2];
            #pragma unroll
            for (int g = 0; g < 8; g++) {
                int ocl = wn * 64 + g * 8 + nl;
                bf[g][0] = w_s[(tp * 8 + jl    ) * 136 + ocl];
                bf[g][1] = w_s[(tp * 8 + jl + 4) * 136 + ocl];
            }
            const int rr = wm + ky;
            #pragma unroll
            for (int f = 0; f < 2; f++) {
                int col = f * 16 + nl + kx;
                const uint32_t* p0 = in_s + jl * 216 + rr * 36 + col;
                const uint32_t* p1 = in_s + (jl + 4) * 216 + rr * 36 + col;
                uint32_t a0 = p0[0], a1 = p0[8], a2 = p1[0], a3 = p1[8];
                #pragma unroll
                for (int g = 0; g < 8; g++) {
                    asm volatile(
                        "mma.sync.aligned.m16n8k16.row.col.f32.f16.f16.f32 "
                        "{%0,%1,%2,%3}, {%4,%5,%6,%7}, {%8,%9}, {%0,%1,%2,%3};"
                        : "+f"(acc[f][g][0]), "+f"(acc[f][g][1]),
                          "+f"(acc[f][g][2]), "+f"(acc[f][g][3])
                        : "r"(a0), "r"(a1), "r"(a2), "r"(a3),
                          "r"(bf[g][0]), "r"(bf[g][1]));
                }
            }
        }
        __syncthreads();
    }

    // ---- epilogue: stage C tile in smem (aliases pipeline buffers) ----
    #pragma unroll
    for (int f = 0; f < 2; f++) {
        #pragma unroll
        for (int g = 0; g < 8; g++) {
            int mloc = wm * 32 + f * 16 + nl;
            int ocl  = wn * 64 + g * 8 + 2 * (lane & 3);
            *(float2*)&Cs[mloc * 132 + ocl]       = make_float2(acc[f][g][0], acc[f][g][1]);
            *(float2*)&Cs[(mloc + 8) * 132 + ocl] = make_float2(acc[f][g][2], acc[f][g][3]);
        }
    }
    __syncthreads();

    // ---- gates: each thread handles 16 (px, el) quads ----
    __half* padh_h = (__half*)padh_w;
    #pragma unroll
    for (int i = 0; i < 16; i++) {
        int q  = i * 256 + t;
        int el = q & 31, px = q >> 5;
        int row = px >> 5, x = px & 31;
        int y = y0 + row;
        float ci = Cs[px * 132 + el];
        float cf = Cs[px * 132 + 32 + el];
        float co = Cs[px * 132 + 64 + el];
        float cg = Cs[px * 132 + 96 + el];
        int e  = eg * 32 + el;
        int pb = b * 1024 + y * 32 + x;
        float c  = g_c[pb * 128 + e];
        float si = 1.0f / (1.0f + expf(-ci));
        float sf = 1.0f / (1.0f + expf(-cf));
        float so = 1.0f / (1.0f + expf(-co));
        float cn = sf * c + si * tanhf(cg);
        float hn = so * tanhf(cn);
        g_c[pb * 128 + e] = cn;
        out[((b * 16 + s) * 1024 + y * 32 + x) * 128 + e] = hn;
        int chunk_h = e >> 4, j = (e & 15) >> 1, pos = e & 1;
        padh_h[((((b * 8 + chunk_h) * CHW) + j * JPL + (y + 1) * 36 + (x + 1)) << 1) | pos]
            = __float2half_rn(hn);
    }
}

// ---------------- launch ----------------------------------------------------
extern "C" void kernel_launch(void* const* d_in, const int* in_sizes, int n_in,
                              void* d_out, int out_size)
{
    const float* inputs = (const float*)d_in[0];
    const float* W_proj = (const float*)d_in[1];
    const float* gamma  = (const float*)d_in[2];
    const float* beta   = (const float*)d_in[3];
    const float* W_in   = (const float*)d_in[4];
    const float* W_out  = (const float*)d_in[5];
    const float* convk  = (const float*)d_in[6];
    float* out = (float*)d_out;

    const int GEMM_SMEM = (16896 + 17408) * 4;       // 137216
    const int ATTN_SMEM = 32 * 388 * 4;              // 49664
    const int CONV_SMEM = (2 * 1728 + 2 * 9792) * 4; // 92160
    cudaFuncSetAttribute(front_fused_kernel, cudaFuncAttributeMaxDynamicSharedMemorySize, GEMM_SMEM);
    cudaFuncSetAttribute(gemm_out_pack_kernel, cudaFuncAttributeMaxDynamicSharedMemorySize, GEMM_SMEM);
    cudaFuncSetAttribute(attn_kernel2, cudaFuncAttributeMaxDynamicSharedMemorySize, ATTN_SMEM);
    cudaFuncSetAttribute(conv_fused_kernel, cudaFuncAttributeMaxDynamicSharedMemorySize, CONV_SMEM);

    // 1) fused: silu(inputs@W_proj) -> LN -> @W_in -> g_qkv
    front_fused_kernel<<<NTOK / 128, 256, GEMM_SMEM>>>(inputs, W_proj, W_in, gamma, beta);
    // 2) attention
    attn_kernel2<<<BB * HH * (WW / 2), 256, ATTN_SMEM>>>();
    // 3) out GEMM + residual, packed straight into g_padx
    gemm_out_pack_kernel<<<NTOK / 128, 256, GEMM_SMEM>>>(W_out, inputs);
    // 4) init: zero c + padh buf0, pack weights
    zero_init_kernel<<<(NPIX * EE + BB * SBW) / 256, 256>>>();
    wprep_kernel<<<(16 * 9 * 8 * 512) / 256, 256>>>(convk);
    // 5) ConvLSTM scan: one fused kernel per step, ping-pong h buffers
    for (int s = 0; s < SS; s++) {
        conv_fused_kernel<<<dim3(4, 8, 8), 256, CONV_SMEM>>>(s, out);
    }
}

// round 14
// speedup vs baseline: 1.9889x; 1.0349x over previous
#include <cuda_runtime.h>
#include <cuda_fp16.h>
#include <math.h>
#include <stdint.h>

// Problem dims
#define BB 8
#define SS 16
#define HH 32
#define WW 32
#define EE 128
#define NTOK (BB*SS*HH*WW)      // 131072
#define NPIX (BB*HH*WW)          // 8192

// conv planar layout (half2 words): [chunk][j8][34 rows][36 cols]
#define JPL   1224               // 34*36 half2 per j-plane
#define CHW   9792               // 8*JPL per chunk (16 ic)
#define SBW   78336              // 8 chunks per (s,b) x-part
#define AST   68                 // half2-word stride for GEMM A/B tiles

// ---------------- scratch (device globals) ----------------------------------
__device__ __align__(16) uint32_t g_qkvh[NTOK*192];   // qkv fp16 (96 MB)
__device__ __align__(16) uint32_t g_aoh [NTOK*64];    // attn out fp16 (32 MB)
__device__ float g_c  [NPIX*EE];
__device__ __align__(16) uint32_t g_padx[SS*BB*SBW];  // 40 MB: x, all steps
__device__ __align__(16) uint32_t g_padh[2*BB*SBW];   // h, ping-pong
__device__ __align__(16) uint32_t g_w2h [16*9*8*512]; // [chunk16][tap9][j8][oc'512]

__device__ __forceinline__ uint32_t sm_u32(const void* p) {
    return (uint32_t)__cvta_generic_to_shared(p);
}
__device__ __forceinline__ void cpa16(uint32_t dst, const void* src) {
    asm volatile("cp.async.cg.shared.global [%0], [%1], 16;\n" :: "r"(dst), "l"(src));
}
__device__ __forceinline__ uint32_t pack_h2(float a, float b) {
    __half2 h = __halves2half2(__float2half_rn(a), __float2half_rn(b));
    return *(uint32_t*)&h;
}
__device__ __forceinline__ float2 unpack_h2(uint32_t u) {
    __half2 h = *(__half2*)&u;
    return __half22float2(h);
}

#define MMA_F16(acc, af, bf)                                               \
    asm volatile(                                                          \
        "mma.sync.aligned.m16n8k16.row.col.f32.f16.f16.f32 "               \
        "{%0,%1,%2,%3}, {%4,%5,%6,%7}, {%8,%9}, {%0,%1,%2,%3};"            \
        : "+f"(acc[0]), "+f"(acc[1]), "+f"(acc[2]), "+f"(acc[3])           \
        : "r"(af[0]), "r"(af[1]), "r"(af[2]), "r"(af[3]),                  \
          "r"(bf[0]), "r"(bf[1]))

// ---- shared fp16 GEMM helpers (A [row][kpair] str AST, B [n][kpair] str AST)
// A frag: rows (lane>>2, +8); kpairs step*8 + (lane&3), +4
// B frag: n = lane>>2; kpairs step*8 + (lane&3), +4

// ---------------- fused front: silu(in@Wp) -> LN -> @W_in -> g_qkvh ---------
// smem: R1 = A half2 (8704 w), R2 = B half2 (8704 w), R3 = LN'd x half2 (8704 w)
// Xs fp32 (128 x 132) aliases R1+R2 between GEMM1 and LN.
__global__ void __launch_bounds__(256) front_fused_kernel(
    const float* __restrict__ inputs, const float* __restrict__ Wp,
    const float* __restrict__ Win,
    const float* __restrict__ gamma, const float* __restrict__ beta)
{
    extern __shared__ uint32_t fsm[];
    uint32_t* Ah = fsm;            // R1
    uint32_t* Bh = fsm + 8704;     // R2
    uint32_t* Xh = fsm + 17408;    // R3
    float*    Xs = (float*)fsm;    // alias R1+R2: 128 x 132 fp32

    const int m0 = blockIdx.x * 128;
    const int t = threadIdx.x, lane = t & 31, warp = t >> 5;
    const int wm = warp & 3, wn = warp >> 2;

    // load A (inputs fp32 -> half2 [row][kpair])
    #pragma unroll
    for (int j = 0; j < 16; j++) {
        int idx = t + j * 256;
        int row = idx >> 5, c4 = idx & 31;
        float4 v = *(const float4*)&inputs[(m0 + row) * 128 + c4 * 4];
        Ah[row * AST + c4 * 2]     = pack_h2(v.x, v.y);
        Ah[row * AST + c4 * 2 + 1] = pack_h2(v.z, v.w);
    }
    // load B (Wp [k][n] -> half2 [n][kpair])
    #pragma unroll
    for (int i = 0; i < 32; i++) {
        int idx = t + i * 256;
        int n = idx & 127, kp = idx >> 7;
        Bh[n * AST + kp] = pack_h2(Wp[(2 * kp) * 128 + n], Wp[(2 * kp + 1) * 128 + n]);
    }
    __syncthreads();

    // GEMM 1: x = inputs @ W_proj
    float acc[2][8][4] = {};
    #pragma unroll
    for (int st = 0; st < 8; st++) {
        uint32_t af[2][4], bf[8][2];
        #pragma unroll
        for (int mi = 0; mi < 2; mi++) {
            int base = (wm * 32 + mi * 16 + (lane >> 2)) * AST + st * 8 + (lane & 3);
            af[mi][0] = Ah[base];
            af[mi][1] = Ah[base + 8 * AST];
            af[mi][2] = Ah[base + 4];
            af[mi][3] = Ah[base + 8 * AST + 4];
        }
        #pragma unroll
        for (int ni = 0; ni < 8; ni++) {
            int b = (wn * 64 + ni * 8 + (lane >> 2)) * AST + st * 8 + (lane & 3);
            bf[ni][0] = Bh[b];
            bf[ni][1] = Bh[b + 4];
        }
        #pragma unroll
        for (int mi = 0; mi < 2; mi++)
            #pragma unroll
            for (int ni = 0; ni < 8; ni++)
                MMA_F16(acc[mi][ni], af[mi], bf[ni]);
    }
    __syncthreads();   // A/B reads done before Xs alias writes

    // silu -> stage fp32 x into Xs
    #pragma unroll
    for (int mi = 0; mi < 2; mi++)
        #pragma unroll
        for (int ni = 0; ni < 8; ni++) {
            int r = wm * 32 + mi * 16 + (lane >> 2);
            int cc = wn * 64 + ni * 8 + 2 * (lane & 3);
            float2 v0 = {acc[mi][ni][0], acc[mi][ni][1]};
            float2 v1 = {acc[mi][ni][2], acc[mi][ni][3]};
            v0.x = v0.x / (1.0f + expf(-v0.x)); v0.y = v0.y / (1.0f + expf(-v0.y));
            v1.x = v1.x / (1.0f + expf(-v1.x)); v1.y = v1.y / (1.0f + expf(-v1.y));
            *(float2*)&Xs[r * 132 + cc]       = v0;
            *(float2*)&Xs[(r + 8) * 132 + cc] = v1;
        }
    __syncthreads();

    // LayerNorm rows -> Xh (half2 [row][kpair])
    {
        float4 g4 = *(const float4*)&gamma[lane * 4];
        float4 b4 = *(const float4*)&beta [lane * 4];
        for (int rl = 0; rl < 16; rl++) {
            int row = warp * 16 + rl;
            float4 v = *(float4*)&Xs[row * 132 + lane * 4];
            float s = v.x + v.y + v.z + v.w;
            float q = v.x * v.x + v.y * v.y + v.z * v.z + v.w * v.w;
            #pragma unroll
            for (int off = 16; off > 0; off >>= 1) {
                s += __shfl_xor_sync(0xFFFFFFFF, s, off);
                q += __shfl_xor_sync(0xFFFFFFFF, q, off);
            }
            float mu  = s * (1.0f / 128.0f);
            float var = q * (1.0f / 128.0f) - mu * mu;
            float rs  = rsqrtf(var + 1e-5f);
            float nx = (v.x - mu) * rs * g4.x + b4.x;
            float ny = (v.y - mu) * rs * g4.y + b4.y;
            float nz = (v.z - mu) * rs * g4.z + b4.z;
            float nw = (v.w - mu) * rs * g4.w + b4.w;
            Xh[row * AST + lane * 2]     = pack_h2(nx, ny);
            Xh[row * AST + lane * 2 + 1] = pack_h2(nz, nw);
        }
    }
    __syncthreads();

    // GEMM 2: qkv = x @ W_in, 3 column tiles (B into R2; Xs dead)
    for (int nt = 0; nt < 3; nt++) {
        #pragma unroll
        for (int i = 0; i < 32; i++) {
            int idx = t + i * 256;
            int n = idx & 127, kp = idx >> 7;
            Bh[n * AST + kp] = pack_h2(Win[(2 * kp) * 384 + nt * 128 + n],
                                       Win[(2 * kp + 1) * 384 + nt * 128 + n]);
        }
        __syncthreads();

        float a2[2][8][4] = {};
        #pragma unroll
        for (int st = 0; st < 8; st++) {
            uint32_t af[2][4], bf[8][2];
            #pragma unroll
            for (int mi = 0; mi < 2; mi++) {
                int base = (wm * 32 + mi * 16 + (lane >> 2)) * AST + st * 8 + (lane & 3);
                af[mi][0] = Xh[base];
                af[mi][1] = Xh[base + 8 * AST];
                af[mi][2] = Xh[base + 4];
                af[mi][3] = Xh[base + 8 * AST + 4];
            }
            #pragma unroll
            for (int ni = 0; ni < 8; ni++) {
                int b = (wn * 64 + ni * 8 + (lane >> 2)) * AST + st * 8 + (lane & 3);
                bf[ni][0] = Bh[b];
                bf[ni][1] = Bh[b + 4];
            }
            #pragma unroll
            for (int mi = 0; mi < 2; mi++)
                #pragma unroll
                for (int ni = 0; ni < 8; ni++)
                    MMA_F16(a2[mi][ni], af[mi], bf[ni]);
        }

        #pragma unroll
        for (int mi = 0; mi < 2; mi++)
            #pragma unroll
            for (int ni = 0; ni < 8; ni++) {
                int r0 = m0 + wm * 32 + mi * 16 + (lane >> 2);
                int cc = wn * 64 + ni * 8 + 2 * (lane & 3);
                int wcol = nt * 64 + (cc >> 1);
                g_qkvh[r0 * 192 + wcol]       = pack_h2(a2[mi][ni][0], a2[mi][ni][1]);
                g_qkvh[(r0 + 8) * 192 + wcol] = pack_h2(a2[mi][ni][2], a2[mi][ni][3]);
            }
        __syncthreads();
    }
}

// ---------------- Attention: fp16 qkv in, fp32 smem compute, fp16 ao out ----
__global__ void __launch_bounds__(256) attn_kernel2()
{
    extern __shared__ float qs[];          // 32 rows x stride 388 (fp32)
    const int bid = blockIdx.x;
    const int wp = bid & 15;
    const int h  = (bid >> 4) & 31;
    const int b  = bid >> 9;
    const int w0 = wp * 2;
    const int t  = threadIdx.x;

    #pragma unroll
    for (int j = 0; j < 24; j++) {
        int idx = t + j * 256;             // 0..6143 (32 rows x 192 words)
        int ti = idx / 192, w = idx % 192;
        int s_ = ti >> 1, wl = ti & 1;
        uint32_t u = g_qkvh[(((b * 16 + s_) * 1024) + h * 32 + w0 + wl) * 192 + w];
        float2 f = unpack_h2(u);
        *(float2*)&qs[ti * 388 + 2 * w] = f;
    }
    __syncthreads();

    const int gl = t >> 4, sq = t & 15;
    const int nh = gl & 7, wl = gl >> 3;
    const int ti_q = sq * 2 + wl;
    const float* qrow = &qs[ti_q * 388 + nh * 48];
    float q[16];
    #pragma unroll
    for (int d = 0; d < 16; d++) q[d] = qrow[d];

    float sc[16];
    float mx = -1e30f;
    #pragma unroll
    for (int l = 0; l < 16; l++) {
        const float* krow = &qs[(l * 2 + wl) * 388 + nh * 48 + 16];
        float d = 0.0f;
        #pragma unroll
        for (int dd = 0; dd < 16; dd++) d += q[dd] * krow[dd];
        float m = (l <= sq) ? 1.0f : -1000.0f;
        sc[l] = d * 0.25f + m;
        mx = fmaxf(mx, sc[l]);
    }
    float sum = 0.0f;
    #pragma unroll
    for (int l = 0; l < 16; l++) { sc[l] = expf(sc[l] - mx); sum += sc[l]; }
    float inv = 1.0f / sum;

    float o[16] = {};
    #pragma unroll
    for (int l = 0; l < 16; l++) {
        float pl = sc[l] * inv;
        const float* vrow = &qs[(l * 2 + wl) * 388 + nh * 48 + 32];
        #pragma unroll
        for (int dd = 0; dd < 16; dd++) o[dd] += pl * vrow[dd];
    }
    __syncthreads();
    #pragma unroll
    for (int d = 0; d < 16; d++) qs[ti_q * 388 + nh * 16 + d] = o[d];
    __syncthreads();

    #pragma unroll
    for (int j = 0; j < 8; j++) {
        int idx = t + j * 256;             // 0..2047 (32 rows x 64 words)
        int ti = idx >> 6, w = idx & 63;
        int s_ = ti >> 1, wl2 = ti & 1;
        g_aoh[(((b * 16 + s_) * 1024) + h * 32 + w0 + wl2) * 64 + w]
            = pack_h2(qs[ti * 388 + 2 * w], qs[ti * 388 + 2 * w + 1]);
    }
}

// ---------------- out GEMM (fp16) + residual + pack into g_padx -------------
__global__ void __launch_bounds__(256) gemm_out_pack_kernel(
    const float* __restrict__ Wout, const float* __restrict__ inputs)
{
    extern __shared__ uint32_t osm[];
    uint32_t* Ah = osm;            // 128 x AST
    uint32_t* Bh = osm + 8704;

    const int m0 = blockIdx.x * 128;
    const int t = threadIdx.x, lane = t & 31, warp = t >> 5;
    const int wm = warp & 3, wn = warp >> 2;

    // A: copy g_aoh rows (already half2 k-pairs)
    #pragma unroll
    for (int i = 0; i < 8; i++) {
        int idx = t + i * 256;             // 0..2047 uint4
        int row = idx >> 4, q4 = idx & 15;
        *(uint4*)&Ah[row * AST + q4 * 4] = *(const uint4*)&g_aoh[(m0 + row) * 64 + q4 * 4];
    }
    // B: Wout repack
    #pragma unroll
    for (int i = 0; i < 32; i++) {
        int idx = t + i * 256;
        int n = idx & 127, kp = idx >> 7;
        Bh[n * AST + kp] = pack_h2(Wout[(2 * kp) * 128 + n], Wout[(2 * kp + 1) * 128 + n]);
    }
    __syncthreads();

    float acc[2][8][4] = {};
    #pragma unroll
    for (int st = 0; st < 8; st++) {
        uint32_t af[2][4], bf[8][2];
        #pragma unroll
        for (int mi = 0; mi < 2; mi++) {
            int base = (wm * 32 + mi * 16 + (lane >> 2)) * AST + st * 8 + (lane & 3);
            af[mi][0] = Ah[base];
            af[mi][1] = Ah[base + 8 * AST];
            af[mi][2] = Ah[base + 4];
            af[mi][3] = Ah[base + 8 * AST + 4];
        }
        #pragma unroll
        for (int ni = 0; ni < 8; ni++) {
            int b = (wn * 64 + ni * 8 + (lane >> 2)) * AST + st * 8 + (lane & 3);
            bf[ni][0] = Bh[b];
            bf[ni][1] = Bh[b + 4];
        }
        #pragma unroll
        for (int mi = 0; mi < 2; mi++)
            #pragma unroll
            for (int ni = 0; ni < 8; ni++)
                MMA_F16(acc[mi][ni], af[mi], bf[ni]);
    }

    #pragma unroll
    for (int mi = 0; mi < 2; mi++)
        #pragma unroll
        for (int ni = 0; ni < 8; ni++) {
            int cc = wn * 64 + ni * 8 + 2 * (lane & 3);     // even e
            int chunk = cc >> 4, jp = (cc & 15) >> 1;
            #pragma unroll
            for (int half = 0; half < 2; half++) {
                int r = m0 + wm * 32 + mi * 16 + (lane >> 2) + half * 8;
                float2 rv = *(const float2*)&inputs[r * 128 + cc];
                float vx = acc[mi][ni][half * 2 + 0] + rv.x;
                float vy = acc[mi][ni][half * 2 + 1] + rv.y;
                int b_ = r >> 14, s_ = (r >> 10) & 15, y = (r >> 5) & 31, x = r & 31;
                g_padx[(s_ * 8 + b_) * SBW + (chunk * 8 + jp) * JPL + (y + 1) * 36 + (x + 1)]
                    = pack_h2(vx, vy);
            }
        }
}

// ---------------- init: zero c + padh buf0 in one launch --------------------
__global__ void zero_init_kernel()
{
    int idx = blockIdx.x * 256 + threadIdx.x;   // 1,675,264 exact
    if (idx < NPIX * EE) g_c[idx] = 0.0f;
    else                 g_padh[idx - NPIX * EE] = 0u;
}
// weights: convk[oc][ic][tap] -> g_w2h[chunk16][tap9][j8][oc'512] half2 (ic0, ic0+1)
// oc' = eg*128 + gate*32 + el  <->  oc_orig = gate*128 + eg*32 + el
__global__ void wprep_kernel(const float* __restrict__ convk)
{
    int idx = blockIdx.x * 256 + threadIdx.x;   // 589,824 exact
    int ocp = idx & 511;
    int t2 = idx >> 9;
    int j  = t2 & 7;
    int t3 = t2 >> 3;                           // 0..143
    int tap = t3 % 9;
    int chunk = t3 / 9;                         // 0..15
    int eg   = ocp >> 7;
    int gate = (ocp >> 5) & 3;
    int el   = ocp & 31;
    int oc   = gate * 128 + eg * 32 + el;
    int ic0  = chunk * 16 + 2 * j;
    g_w2h[idx] = pack_h2(convk[(oc * 256 + ic0) * 9 + tap],
                         convk[(oc * 256 + ic0 + 1) * 9 + tap]);
}

// ---------------- fused conv + LSTM gates (padh ping-pong, unchanged) -------
__global__ void __launch_bounds__(256) conv_fused_kernel(int s, float* __restrict__ out)
{
    extern __shared__ uint32_t sh[];
    uint32_t* in_base = sh;                 // 2 x 1728
    uint32_t* w_base  = sh + 2 * 1728;      // 2 x 9792
    float*    Cs      = (float*)sh;         // epilogue alias: 128 x 132

    const int b   = blockIdx.z;
    const int y0  = blockIdx.y * 4;
    const int eg  = blockIdx.x;             // oc' block = eg*128
    const int t    = threadIdx.x;
    const int lane = t & 31;
    const int warp = t >> 5;
    const int wm = warp & 3, wn = warp >> 2;
    const int jl = lane & 3, nl = lane >> 2;

    const uint32_t* padx_b = g_padx + (s * 8 + b) * SBW;
    const uint32_t* padh_r = g_padh + (s & 1) * (BB * SBW) + b * SBW;
    uint32_t*       padh_w = g_padh + ((s + 1) & 1) * (BB * SBW);
    const uint32_t sm_in = sm_u32(in_base);
    const uint32_t sm_w  = sm_u32(w_base);

    auto load_chunk = [&](int stage, int c) {
        const uint32_t* ibase = (c < 8) ? (padx_b + c * CHW) : (padh_r + (c - 8) * CHW);
        uint32_t id = sm_in + (uint32_t)stage * 1728u * 4u;
        #pragma unroll
        for (int k = 0; k < 2; k++) {
            int idx = t + k * 256;
            if (idx < 432) {
                int j = idx / 54, rem = idx % 54;
                int r = rem / 9, c16 = rem % 9;
                cpa16(id + (uint32_t)(j * 216 + r * 36 + c16 * 4) * 4u,
                      ibase + j * JPL + (y0 + r) * 36 + c16 * 4);
            }
        }
        uint32_t wd = sm_w + (uint32_t)stage * 9792u * 4u;
        const uint32_t* wbase = g_w2h + c * 36864 + eg * 128;
        #pragma unroll
        for (int k = 0; k < 9; k++) {
            int idx = t + k * 256;
            int row = idx >> 5, c16 = idx & 31;
            cpa16(wd + (uint32_t)(row * 136 + c16 * 4) * 4u,
                  wbase + row * 512 + c16 * 4);
        }
        asm volatile("cp.async.commit_group;\n");
    };

    float acc[2][8][4] = {};
    load_chunk(0, 0);

    for (int c = 0; c < 16; c++) {
        const int stage = c & 1;
        if (c < 15) {
            load_chunk(stage ^ 1, c + 1);
            asm volatile("cp.async.wait_group 1;\n");
        } else {
            asm volatile("cp.async.wait_group 0;\n");
        }
        __syncthreads();

        const uint32_t* in_s = in_base + stage * 1728;
        const uint32_t* w_s  = w_base  + stage * 9792;

        #pragma unroll
        for (int tp = 0; tp < 9; tp++) {
            const int ky = tp / 3, kx = tp % 3;
            uint32_t bf[8][2];
            #pragma unroll
            for (int g = 0; g < 8; g++) {
                int ocl = wn * 64 + g * 8 + nl;
                bf[g][0] = w_s[(tp * 8 + jl    ) * 136 + ocl];
                bf[g][1] = w_s[(tp * 8 + jl + 4) * 136 + ocl];
            }
            const int rr = wm + ky;
            #pragma unroll
            for (int f = 0; f < 2; f++) {
                int col = f * 16 + nl + kx;
                const uint32_t* p0 = in_s + jl * 216 + rr * 36 + col;
                const uint32_t* p1 = in_s + (jl + 4) * 216 + rr * 36 + col;
                uint32_t a0 = p0[0], a1 = p0[8], a2 = p1[0], a3 = p1[8];
                #pragma unroll
                for (int g = 0; g < 8; g++) {
                    asm volatile(
                        "mma.sync.aligned.m16n8k16.row.col.f32.f16.f16.f32 "
                        "{%0,%1,%2,%3}, {%4,%5,%6,%7}, {%8,%9}, {%0,%1,%2,%3};"
                        : "+f"(acc[f][g][0]), "+f"(acc[f][g][1]),
                          "+f"(acc[f][g][2]), "+f"(acc[f][g][3])
                        : "r"(a0), "r"(a1), "r"(a2), "r"(a3),
                          "r"(bf[g][0]), "r"(bf[g][1]));
                }
            }
        }
        __syncthreads();
    }

    // ---- epilogue: stage C tile in smem (aliases pipeline buffers) ----
    #pragma unroll
    for (int f = 0; f < 2; f++) {
        #pragma unroll
        for (int g = 0; g < 8; g++) {
            int mloc = wm * 32 + f * 16 + nl;
            int ocl  = wn * 64 + g * 8 + 2 * (lane & 3);
            *(float2*)&Cs[mloc * 132 + ocl]       = make_float2(acc[f][g][0], acc[f][g][1]);
            *(float2*)&Cs[(mloc + 8) * 132 + ocl] = make_float2(acc[f][g][2], acc[f][g][3]);
        }
    }
    __syncthreads();

    // ---- gates: each thread handles 16 (px, el) quads ----
    __half* padh_h = (__half*)padh_w;
    #pragma unroll
    for (int i = 0; i < 16; i++) {
        int q  = i * 256 + t;
        int el = q & 31, px = q >> 5;
        int row = px >> 5, x = px & 31;
        int y = y0 + row;
        float ci = Cs[px * 132 + el];
        float cf = Cs[px * 132 + 32 + el];
        float co = Cs[px * 132 + 64 + el];
        float cg = Cs[px * 132 + 96 + el];
        int e  = eg * 32 + el;
        int pb = b * 1024 + y * 32 + x;
        float c  = g_c[pb * 128 + e];
        float si = 1.0f / (1.0f + expf(-ci));
        float sf = 1.0f / (1.0f + expf(-cf));
        float so = 1.0f / (1.0f + expf(-co));
        float cn = sf * c + si * tanhf(cg);
        float hn = so * tanhf(cn);
        g_c[pb * 128 + e] = cn;
        out[((b * 16 + s) * 1024 + y * 32 + x) * 128 + e] = hn;
        int chunk_h = e >> 4, j = (e & 15) >> 1, pos = e & 1;
        padh_h[((((b * 8 + chunk_h) * CHW) + j * JPL + (y + 1) * 36 + (x + 1)) << 1) | pos]
            = __float2half_rn(hn);
    }
}

// ---------------- launch ----------------------------------------------------
extern "C" void kernel_launch(void* const* d_in, const int* in_sizes, int n_in,
                              void* d_out, int out_size)
{
    const float* inputs = (const float*)d_in[0];
    const float* W_proj = (const float*)d_in[1];
    const float* gamma  = (const float*)d_in[2];
    const float* beta   = (const float*)d_in[3];
    const float* W_in   = (const float*)d_in[4];
    const float* W_out  = (const float*)d_in[5];
    const float* convk  = (const float*)d_in[6];
    float* out = (float*)d_out;

    const int FRONT_SMEM = 26112 * 4;                // 104448
    const int OUT_SMEM   = 17408 * 4;                // 69632
    const int ATTN_SMEM  = 32 * 388 * 4;             // 49664
    const int CONV_SMEM  = (2 * 1728 + 2 * 9792) * 4; // 92160
    cudaFuncSetAttribute(front_fused_kernel, cudaFuncAttributeMaxDynamicSharedMemorySize, FRONT_SMEM);
    cudaFuncSetAttribute(gemm_out_pack_kernel, cudaFuncAttributeMaxDynamicSharedMemorySize, OUT_SMEM);
    cudaFuncSetAttribute(attn_kernel2, cudaFuncAttributeMaxDynamicSharedMemorySize, ATTN_SMEM);
    cudaFuncSetAttribute(conv_fused_kernel, cudaFuncAttributeMaxDynamicSharedMemorySize, CONV_SMEM);

    // 1) fused: silu(inputs@W_proj) -> LN -> @W_in -> g_qkvh (fp16)
    front_fused_kernel<<<NTOK / 128, 256, FRONT_SMEM>>>(inputs, W_proj, W_in, gamma, beta);
    // 2) attention (fp16 in/out, fp32 compute)
    attn_kernel2<<<BB * HH * (WW / 2), 256, ATTN_SMEM>>>();
    // 3) out GEMM + residual, packed straight into g_padx
    gemm_out_pack_kernel<<<NTOK / 128, 256, OUT_SMEM>>>(W_out, inputs);
    // 4) init: zero c + padh buf0, pack weights
    zero_init_kernel<<<(NPIX * EE + BB * SBW) / 256, 256>>>();
    wprep_kernel<<<(16 * 9 * 8 * 512) / 256, 256>>>(convk);
    // 5) ConvLSTM scan: one fused kernel per step, ping-pong h buffers
    for (int s = 0; s < SS; s++) {
        conv_fused_kernel<<<dim3(4, 8, 8), 256, CONV_SMEM>>>(s, out);
    }
}